// round 2
// baseline (speedup 1.0000x reference)
#include <cuda_runtime.h>
#include <math.h>

#define T_STEPS 16
#define BATCH   128
#define IN_DIM  12288
#define HH1     256
#define HH2     512

// ---------------- scratch (static __device__ globals; no runtime alloc) ----
__device__ float g_pre1[T_STEPS * BATCH * 4 * HH1];   //  8.4 MB
__device__ float g_y1  [T_STEPS * BATCH * HH1];       //  2.1 MB
__device__ float g_c1  [BATCH * HH1];
__device__ float g_pre2[T_STEPS * BATCH * 4 * HH2];   // 16.8 MB
__device__ float g_c2  [BATCH * HH2];
__device__ float g_zero[BATCH * HH2];                 // never written -> stays 0

// ---------------------------------------------------------------------------
// C[M,N] = A[M,K] @ W[N,K]^T + bias[N]
// A row-major, W row-major (K contiguous in both). BM=BN=128, BK=16,
// 256 threads, 8x8 micro-tile split as (4+4)x(4+4), register double-buffered.
// Requires M%128==0, N%128==0, K%16==0 (true for all calls here).
// ---------------------------------------------------------------------------
template<int BM, int BN, int BK>
__global__ __launch_bounds__(256)
void sgemm_nt_bias(const float* __restrict__ A, const float* __restrict__ W,
                   const float* __restrict__ bias, float* __restrict__ C,
                   int M, int N, int K)
{
    constexpr int LDA = BM + 4;
    constexpr int LDW = BN + 4;
    __shared__ float As[BK * LDA];
    __shared__ float Ws[BK * LDW];

    const int tid = threadIdx.x;
    const int tx  = tid & 15;        // 0..15  (N direction)
    const int ty  = tid >> 4;        // 0..15  (M direction)

    const int lr  = tid >> 2;        // 0..63  load row
    const int lc4 = tid & 3;         // 0..3   float4 column within BK=16

    const int bm0 = blockIdx.y * BM;
    const int bn0 = blockIdx.x * BN;

    const float* Aptr = A + (size_t)(bm0 + lr) * K + lc4 * 4;
    const float* Wptr = W + (size_t)(bn0 + lr) * K + lc4 * 4;

    float acc[2][2][4][4];
#pragma unroll
    for (int ri = 0; ri < 2; ri++)
#pragma unroll
        for (int ci = 0; ci < 2; ci++)
#pragma unroll
            for (int i = 0; i < 4; i++)
#pragma unroll
                for (int j = 0; j < 4; j++)
                    acc[ri][ci][i][j] = 0.f;

    const int KT = K / BK;

    float4 pa0 = *(const float4*)(Aptr);
    float4 pa1 = *(const float4*)(Aptr + (size_t)64 * K);
    float4 pw0 = *(const float4*)(Wptr);
    float4 pw1 = *(const float4*)(Wptr + (size_t)64 * K);

#pragma unroll 1
    for (int kt = 0; kt < KT; kt++) {
        // stage registers -> smem (transposed: [k][m])
        As[(lc4 * 4 + 0) * LDA + lr]      = pa0.x;
        As[(lc4 * 4 + 1) * LDA + lr]      = pa0.y;
        As[(lc4 * 4 + 2) * LDA + lr]      = pa0.z;
        As[(lc4 * 4 + 3) * LDA + lr]      = pa0.w;
        As[(lc4 * 4 + 0) * LDA + lr + 64] = pa1.x;
        As[(lc4 * 4 + 1) * LDA + lr + 64] = pa1.y;
        As[(lc4 * 4 + 2) * LDA + lr + 64] = pa1.z;
        As[(lc4 * 4 + 3) * LDA + lr + 64] = pa1.w;
        Ws[(lc4 * 4 + 0) * LDW + lr]      = pw0.x;
        Ws[(lc4 * 4 + 1) * LDW + lr]      = pw0.y;
        Ws[(lc4 * 4 + 2) * LDW + lr]      = pw0.z;
        Ws[(lc4 * 4 + 3) * LDW + lr]      = pw0.w;
        Ws[(lc4 * 4 + 0) * LDW + lr + 64] = pw1.x;
        Ws[(lc4 * 4 + 1) * LDW + lr + 64] = pw1.y;
        Ws[(lc4 * 4 + 2) * LDW + lr + 64] = pw1.z;
        Ws[(lc4 * 4 + 3) * LDW + lr + 64] = pw1.w;
        __syncthreads();

        // prefetch next tile into registers (overlaps with compute below)
        if (kt + 1 < KT) {
            const float* ap = Aptr + (size_t)(kt + 1) * BK;
            const float* wp = Wptr + (size_t)(kt + 1) * BK;
            pa0 = *(const float4*)(ap);
            pa1 = *(const float4*)(ap + (size_t)64 * K);
            pw0 = *(const float4*)(wp);
            pw1 = *(const float4*)(wp + (size_t)64 * K);
        }

#pragma unroll
        for (int k = 0; k < BK; k++) {
            float4 a0 = *(const float4*)&As[k * LDA + ty * 4];
            float4 a1 = *(const float4*)&As[k * LDA + 64 + ty * 4];
            float4 w0 = *(const float4*)&Ws[k * LDW + tx * 4];
            float4 w1 = *(const float4*)&Ws[k * LDW + 64 + tx * 4];
            float av[2][4] = {{a0.x, a0.y, a0.z, a0.w}, {a1.x, a1.y, a1.z, a1.w}};
            float wv[2][4] = {{w0.x, w0.y, w0.z, w0.w}, {w1.x, w1.y, w1.z, w1.w}};
#pragma unroll
            for (int ri = 0; ri < 2; ri++)
#pragma unroll
                for (int i = 0; i < 4; i++)
#pragma unroll
                    for (int ci = 0; ci < 2; ci++)
#pragma unroll
                        for (int j = 0; j < 4; j++)
                            acc[ri][ci][i][j] += av[ri][i] * wv[ci][j];
        }
        __syncthreads();
    }

    float4 bv0 = *(const float4*)&bias[bn0 + tx * 4];
    float4 bv1 = *(const float4*)&bias[bn0 + 64 + tx * 4];
    float bb[2][4] = {{bv0.x, bv0.y, bv0.z, bv0.w}, {bv1.x, bv1.y, bv1.z, bv1.w}};

#pragma unroll
    for (int ri = 0; ri < 2; ri++)
#pragma unroll
        for (int i = 0; i < 4; i++) {
            int row = bm0 + ri * 64 + ty * 4 + i;
#pragma unroll
            for (int ci = 0; ci < 2; ci++) {
                float4 o;
                o.x = acc[ri][ci][i][0] + bb[ci][0];
                o.y = acc[ri][ci][i][1] + bb[ci][1];
                o.z = acc[ri][ci][i][2] + bb[ci][2];
                o.w = acc[ri][ci][i][3] + bb[ci][3];
                *(float4*)&C[(size_t)row * N + bn0 + ci * 64 + tx * 4] = o;
            }
        }
}

// ---------------------------------------------------------------------------
// One LSTM time step, fused:  g = pre + hprev @ Whh^T ; gates ; c,h update.
// Block: 32 batches x 8 units (x4 gates = 32 W rows). 256 threads.
// Grid: (H/8, B/32).   H in {256, 512}.
// ---------------------------------------------------------------------------
template<int H>
__global__ __launch_bounds__(256)
void lstm_step(const float* __restrict__ pre,    // [B][4H] for this t
               const float* __restrict__ hprev,  // [B][H]
               const float* __restrict__ Whh,    // [4H][H]
               const float* __restrict__ cprev,  // [B][H]
               float* __restrict__ cout,         // [B][H]
               float* __restrict__ hout)         // [B][H]
{
    constexpr int BB = 32, GU = 8, KC = 64;
    __shared__ float hs[BB * (KC + 1)];   // [b][kk]
    __shared__ float ws[KC * 36];         // [kk][row_local], padded for LDS.128
    __shared__ float gsm[4 * GU * 33];    // [row_local][b]

    const int tid = threadIdx.x;
    const int u0 = blockIdx.x * GU;
    const int b0 = blockIdx.y * BB;

    const int b  = tid & 31;   // compute batch
    const int rg = tid >> 5;   // 0..7 -> rows rg*4..rg*4+3

    // fill-phase mapping (lane-transposed: conflict-free STS)
    const int fr = tid & 31;   // row_local (ws) / batch (hs)
    const int kg = tid >> 5;   // 0..7 -> kk = kg*8..kg*8+7
    const int gate = fr >> 3;  // row_local / GU
    const int ul_f = fr & 7;
    const float* wrow = Whh + (size_t)(gate * H + u0 + ul_f) * H;
    const float* hrow = hprev + (size_t)(b0 + fr) * H;

    float a0 = 0.f, a1 = 0.f, a2 = 0.f, a3 = 0.f;

    for (int k0 = 0; k0 < H; k0 += KC) {
        __syncthreads();
        {
            float4 wa = *(const float4*)(wrow + k0 + kg * 8);
            float4 wb = *(const float4*)(wrow + k0 + kg * 8 + 4);
            ws[(kg * 8 + 0) * 36 + fr] = wa.x;
            ws[(kg * 8 + 1) * 36 + fr] = wa.y;
            ws[(kg * 8 + 2) * 36 + fr] = wa.z;
            ws[(kg * 8 + 3) * 36 + fr] = wa.w;
            ws[(kg * 8 + 4) * 36 + fr] = wb.x;
            ws[(kg * 8 + 5) * 36 + fr] = wb.y;
            ws[(kg * 8 + 6) * 36 + fr] = wb.z;
            ws[(kg * 8 + 7) * 36 + fr] = wb.w;
            float4 ha = *(const float4*)(hrow + k0 + kg * 8);
            float4 hb = *(const float4*)(hrow + k0 + kg * 8 + 4);
            hs[fr * (KC + 1) + kg * 8 + 0] = ha.x;
            hs[fr * (KC + 1) + kg * 8 + 1] = ha.y;
            hs[fr * (KC + 1) + kg * 8 + 2] = ha.z;
            hs[fr * (KC + 1) + kg * 8 + 3] = ha.w;
            hs[fr * (KC + 1) + kg * 8 + 4] = hb.x;
            hs[fr * (KC + 1) + kg * 8 + 5] = hb.y;
            hs[fr * (KC + 1) + kg * 8 + 6] = hb.z;
            hs[fr * (KC + 1) + kg * 8 + 7] = hb.w;
        }
        __syncthreads();
#pragma unroll
        for (int kk = 0; kk < KC; kk++) {
            float hv = hs[b * (KC + 1) + kk];
            float4 wv = *(const float4*)&ws[kk * 36 + rg * 4];  // broadcast
            a0 += hv * wv.x;
            a1 += hv * wv.y;
            a2 += hv * wv.z;
            a3 += hv * wv.w;
        }
    }

    // exchange partial gate values so each thread owns one (b, unit) cell
    gsm[(rg * 4 + 0) * 33 + b] = a0;
    gsm[(rg * 4 + 1) * 33 + b] = a1;
    gsm[(rg * 4 + 2) * 33 + b] = a2;
    gsm[(rg * 4 + 3) * 33 + b] = a3;
    __syncthreads();

    const int bb2 = tid & 31;
    const int ul  = tid >> 5;  // 0..7
    const float* prow = pre + (size_t)(b0 + bb2) * 4 * H + u0 + ul;
    float gi = prow[0]     + gsm[(0 * GU + ul) * 33 + bb2];
    float gf = prow[H]     + gsm[(1 * GU + ul) * 33 + bb2];
    float gg = prow[2 * H] + gsm[(2 * GU + ul) * 33 + bb2];
    float go = prow[3 * H] + gsm[(3 * GU + ul) * 33 + bb2];

    float si = 1.f / (1.f + __expf(-gi));
    float sf = 1.f / (1.f + __expf(-gf));
    float so = 1.f / (1.f + __expf(-go));
    float tg = tanhf(gg);

    const int ci = (b0 + bb2) * H + u0 + ul;
    float cn = sf * cprev[ci] + si * tg;
    cout[ci] = cn;
    hout[ci] = so * tanhf(cn);
}

// ---------------------------------------------------------------------------
extern "C" void kernel_launch(void* const* d_in, const int* in_sizes, int n_in,
                              void* d_out, int out_size)
{
    const float* inp  = (const float*)d_in[0];  // [B,T,IN] flat == [T*B, IN]
    const float* Wih1 = (const float*)d_in[1];  // [4H1, IN]
    const float* Whh1 = (const float*)d_in[2];  // [4H1, H1]
    const float* b1   = (const float*)d_in[3];  // [4H1]
    const float* Wih2 = (const float*)d_in[4];  // [4H2, H1]
    const float* Whh2 = (const float*)d_in[5];  // [4H2, H2]
    const float* b2   = (const float*)d_in[6];  // [4H2]
    float* out = (float*)d_out;                 // flat [T][B][H2]

    float *pre1, *y1, *c1, *pre2, *c2, *zero;
    cudaGetSymbolAddress((void**)&pre1, g_pre1);
    cudaGetSymbolAddress((void**)&y1,   g_y1);
    cudaGetSymbolAddress((void**)&c1,   g_c1);
    cudaGetSymbolAddress((void**)&pre2, g_pre2);
    cudaGetSymbolAddress((void**)&c2,   g_c2);
    cudaGetSymbolAddress((void**)&zero, g_zero);

    const int M = T_STEPS * BATCH;  // 2048

    // Layer 1 input projection: pre1 = X @ Wih1^T + b1   [2048 x 1024], K=12288
    sgemm_nt_bias<128, 128, 16>
        <<<dim3(4 * HH1 / 128, M / 128), 256>>>(inp, Wih1, b1, pre1, M, 4 * HH1, IN_DIM);

    // Layer 1 recurrence
    for (int t = 0; t < T_STEPS; t++) {
        const float* hp = (t == 0) ? zero : (y1 + (size_t)(t - 1) * BATCH * HH1);
        const float* cp = (t == 0) ? zero : c1;
        lstm_step<HH1><<<dim3(HH1 / 8, BATCH / 32), 256>>>(
            pre1 + (size_t)t * BATCH * 4 * HH1, hp, Whh1, cp, c1,
            y1 + (size_t)t * BATCH * HH1);
    }

    // Layer 2 input projection: pre2 = Y1 @ Wih2^T + b2   [2048 x 2048], K=256
    sgemm_nt_bias<128, 128, 16>
        <<<dim3(4 * HH2 / 128, M / 128), 256>>>(y1, Wih2, b2, pre2, M, 4 * HH2, HH1);

    // Layer 2 recurrence (h written straight into d_out, read back as hprev)
    for (int t = 0; t < T_STEPS; t++) {
        const float* hp = (t == 0) ? zero : (out + (size_t)(t - 1) * BATCH * HH2);
        const float* cp = (t == 0) ? zero : c2;
        lstm_step<HH2><<<dim3(HH2 / 8, BATCH / 32), 256>>>(
            pre2 + (size_t)t * BATCH * 4 * HH2, hp, Whh2, cp, c2,
            out + (size_t)t * BATCH * HH2);
    }
}

// round 6
// speedup vs baseline: 1.6956x; 1.6956x over previous
#include <cuda_runtime.h>
#include <cuda_bf16.h>
#include <cstdint>
#include <math.h>

#define T_STEPS 16
#define BATCH   128
#define IN_DIM  12288
#define HH1     256
#define HH2     512

// ---------------- scratch (static __device__ globals; no runtime alloc) ----
__device__ float g_pre1[T_STEPS * BATCH * 4 * HH1];   //  8.4 MB
__device__ float g_y1  [T_STEPS * BATCH * HH1];       //  2.1 MB
__device__ float g_c1  [BATCH * HH1];
__device__ float g_pre2[T_STEPS * BATCH * 4 * HH2];   // 16.8 MB
__device__ float g_c2  [BATCH * HH2];
__device__ float g_zero[BATCH * HH2];                 // never written -> stays 0

// split-bf16 staging for the big layer-1 GEMM
__device__ __nv_bfloat16 g_Ahi[T_STEPS * BATCH * IN_DIM];   // 50 MB
__device__ __nv_bfloat16 g_Alo[T_STEPS * BATCH * IN_DIM];   // 50 MB
__device__ __nv_bfloat16 g_Whi[4 * HH1 * IN_DIM];           // 25 MB
__device__ __nv_bfloat16 g_Wlo[4 * HH1 * IN_DIM];           // 25 MB

// ===========================================================================
// helpers
// ===========================================================================
__device__ __forceinline__ uint32_t smem_u32(const void* p) {
    uint32_t a;
    asm("{ .reg .u64 t; cvta.to.shared.u64 t, %1; cvt.u32.u64 %0, t; }"
        : "=r"(a) : "l"(p));
    return a;
}

#define LDSM_X4(r, addr) \
    asm volatile("ldmatrix.sync.aligned.m8n8.x4.shared.b16 {%0,%1,%2,%3}, [%4];" \
        : "=r"((r)[0]), "=r"((r)[1]), "=r"((r)[2]), "=r"((r)[3]) : "r"(addr))

#define MMA16816(d, a, b0v, b1v) \
    asm volatile("mma.sync.aligned.m16n8k16.row.col.f32.bf16.bf16.f32 " \
        "{%0,%1,%2,%3}, {%4,%5,%6,%7}, {%8,%9}, {%0,%1,%2,%3};" \
        : "+f"((d)[0]), "+f"((d)[1]), "+f"((d)[2]), "+f"((d)[3]) \
        : "r"((a)[0]), "r"((a)[1]), "r"((a)[2]), "r"((a)[3]), \
          "r"(b0v), "r"(b1v))

#define CP_ASYNC16(dst, src) \
    asm volatile("cp.async.cg.shared.global [%0], [%1], 16;" \
        :: "r"(dst), "l"(src))
#define CP_COMMIT() asm volatile("cp.async.commit_group;" ::: "memory")
#define CP_WAIT1()  asm volatile("cp.async.wait_group 1;"  ::: "memory")

// ===========================================================================
// fp32 -> (hi, lo) bf16 split
// ===========================================================================
__global__ __launch_bounds__(256)
void split_bf16(const float* __restrict__ x, __nv_bfloat16* __restrict__ hi,
                __nv_bfloat16* __restrict__ lo, int n4) {
    int i = blockIdx.x * blockDim.x + threadIdx.x;
    if (i >= n4) return;
    float4 v = ((const float4*)x)[i];
    float vv[4] = {v.x, v.y, v.z, v.w};
    __align__(8) __nv_bfloat16 h[4], l[4];
#pragma unroll
    for (int j = 0; j < 4; j++) {
        h[j] = __float2bfloat16(vv[j]);
        l[j] = __float2bfloat16(vv[j] - __bfloat162float(h[j]));
    }
    ((uint2*)hi)[i] = *(uint2*)h;
    ((uint2*)lo)[i] = *(uint2*)l;
}

// ===========================================================================
// split-bf16 GEMM on mma.sync:  C[M,N] = A[M,K] @ W[N,K]^T + bias[N]
// 128x128 CTA tile, BK=64 bf16 (128B rows, XOR-8 swizzle), 2-stage cp.async.
// 8 warps as 4(m) x 2(n); warp tile 32x64; 3 passes: hh + h*lo + lo*h.
// ===========================================================================
#define MT_BYTES   16384                 // one 128x64 bf16 tile
#define STAGE_B    (4 * MT_BYTES)        // Ahi, Alo, Whi, Wlo
#define GEMM_SMEM  (2 * STAGE_B)         // 128 KB

__global__ __launch_bounds__(256, 1)
void gemm_mma_split(const __nv_bfloat16* __restrict__ Ahi,
                    const __nv_bfloat16* __restrict__ Alo,
                    const __nv_bfloat16* __restrict__ Whi,
                    const __nv_bfloat16* __restrict__ Wlo,
                    const float* __restrict__ bias,
                    float* __restrict__ C,
                    int N, int K)
{
    extern __shared__ __align__(1024) char smem[];
    const uint32_t sb = smem_u32(smem);

    const int tid  = threadIdx.x;
    const int lane = tid & 31;
    const int wid  = tid >> 5;
    const int warp_m = wid & 3;          // 0..3  (rows, 32 each)
    const int warp_n = wid >> 2;         // 0..1  (cols, 64 each)
    const int bm0 = blockIdx.y * 128;
    const int bn0 = blockIdx.x * 128;

    // loader mapping: 256 threads -> (row, 16B-chunk); 4 row-iters cover 128
    const int lr = tid >> 3;             // 0..31
    const int lc = tid & 7;              // 0..7

    const __nv_bfloat16* srcA[2] = { Ahi + (size_t)bm0 * K,  Alo + (size_t)bm0 * K };
    const __nv_bfloat16* srcW[2] = { Whi + (size_t)bn0 * K,  Wlo + (size_t)bn0 * K };

    const int NC = K / 64;

    auto issue_stage = [&](int kc, int stage) {
        const size_t koff = (size_t)kc * 64;
        const uint32_t stb = sb + stage * STAGE_B;
#pragma unroll
        for (int t = 0; t < 4; t++) {
            const __nv_bfloat16* base =
                (t < 2) ? srcA[t] : srcW[t - 2];
            const uint32_t tb = stb + t * MT_BYTES;
#pragma unroll
            for (int i = 0; i < 4; i++) {
                int rr = lr + i * 32;
                const __nv_bfloat16* src = base + (size_t)rr * K + koff + lc * 8;
                uint32_t dst = tb + rr * 128 + ((lc ^ (rr & 7)) * 16);
                CP_ASYNC16(dst, src);
            }
        }
    };

    float acc[2][8][4];
#pragma unroll
    for (int mt = 0; mt < 2; mt++)
#pragma unroll
        for (int nt = 0; nt < 8; nt++)
#pragma unroll
            for (int j = 0; j < 4; j++)
                acc[mt][nt][j] = 0.f;

    // ldmatrix per-lane address components
    const int arow  = warp_m * 32 + (lane & 15);               // + mt*16
    const int ahalf = lane >> 4;                               // 16B half of k16
    const int brow  = warp_n * 64 + ((lane >> 4) << 3) + (lane & 7);  // + nt2*16
    const int bhalf = (lane >> 3) & 1;

    issue_stage(0, 0);
    CP_COMMIT();

#pragma unroll 1
    for (int kc = 0; kc < NC; kc++) {
        const int buf = kc & 1;
        if (kc + 1 < NC) issue_stage(kc + 1, buf ^ 1);
        CP_COMMIT();
        CP_WAIT1();
        __syncthreads();

        const uint32_t stb = sb + buf * STAGE_B;
        const uint32_t tAh = stb;
        const uint32_t tAl = stb + MT_BYTES;
        const uint32_t tWh = stb + 2 * MT_BYTES;
        const uint32_t tWl = stb + 3 * MT_BYTES;

#pragma unroll
        for (int ks = 0; ks < 4; ks++) {
            uint32_t ahi[2][4], alo[2][4], bhi[4][4], blo[4][4];
#pragma unroll
            for (int mt = 0; mt < 2; mt++) {
                int r  = arow + mt * 16;
                int ch = 2 * ks + ahalf;
                uint32_t off = r * 128 + ((ch ^ (r & 7)) * 16);
                LDSM_X4(ahi[mt], tAh + off);
                LDSM_X4(alo[mt], tAl + off);
            }
#pragma unroll
            for (int nt2 = 0; nt2 < 4; nt2++) {
                int r  = brow + nt2 * 16;
                int ch = 2 * ks + bhalf;
                uint32_t off = r * 128 + ((ch ^ (r & 7)) * 16);
                LDSM_X4(bhi[nt2], tWh + off);
                LDSM_X4(blo[nt2], tWl + off);
            }
#pragma unroll
            for (int mt = 0; mt < 2; mt++)
#pragma unroll
                for (int nt = 0; nt < 8; nt++) {
                    const uint32_t* bh = &bhi[nt >> 1][(nt & 1) * 2];
                    const uint32_t* bl = &blo[nt >> 1][(nt & 1) * 2];
                    MMA16816(acc[mt][nt], ahi[mt], bh[0], bh[1]);
                    MMA16816(acc[mt][nt], ahi[mt], bl[0], bl[1]);
                    MMA16816(acc[mt][nt], alo[mt], bh[0], bh[1]);
                }
        }
        __syncthreads();
    }

    // epilogue: c-frag (m16n8): rows lane>>2 (+8), cols (lane&3)*2
#pragma unroll
    for (int mt = 0; mt < 2; mt++) {
        int row0 = bm0 + warp_m * 32 + mt * 16 + (lane >> 2);
#pragma unroll
        for (int nt = 0; nt < 8; nt++) {
            int col = bn0 + warp_n * 64 + nt * 8 + (lane & 3) * 2;
            float b0 = bias[col], b1 = bias[col + 1];
            float2 o0 = { acc[mt][nt][0] + b0, acc[mt][nt][1] + b1 };
            float2 o1 = { acc[mt][nt][2] + b0, acc[mt][nt][3] + b1 };
            *(float2*)&C[(size_t)row0 * N + col]       = o0;
            *(float2*)&C[(size_t)(row0 + 8) * N + col] = o1;
        }
    }
}

// ---------------------------------------------------------------------------
// fp32 SGEMM (layer-2 input projection, K=256)
// ---------------------------------------------------------------------------
template<int BM, int BN, int BK>
__global__ __launch_bounds__(256)
void sgemm_nt_bias(const float* __restrict__ A, const float* __restrict__ W,
                   const float* __restrict__ bias, float* __restrict__ C,
                   int M, int N, int K)
{
    constexpr int LDA = BM + 4;
    constexpr int LDW = BN + 4;
    __shared__ float As[BK * LDA];
    __shared__ float Ws[BK * LDW];

    const int tid = threadIdx.x;
    const int tx  = tid & 15;
    const int ty  = tid >> 4;
    const int lr  = tid >> 2;
    const int lc4 = tid & 3;
    const int bm0 = blockIdx.y * BM;
    const int bn0 = blockIdx.x * BN;

    const float* Aptr = A + (size_t)(bm0 + lr) * K + lc4 * 4;
    const float* Wptr = W + (size_t)(bn0 + lr) * K + lc4 * 4;

    float acc[2][2][4][4];
#pragma unroll
    for (int ri = 0; ri < 2; ri++)
#pragma unroll
        for (int ci = 0; ci < 2; ci++)
#pragma unroll
            for (int i = 0; i < 4; i++)
#pragma unroll
                for (int j = 0; j < 4; j++)
                    acc[ri][ci][i][j] = 0.f;

    const int KT = K / BK;
    float4 pa0 = *(const float4*)(Aptr);
    float4 pa1 = *(const float4*)(Aptr + (size_t)64 * K);
    float4 pw0 = *(const float4*)(Wptr);
    float4 pw1 = *(const float4*)(Wptr + (size_t)64 * K);

#pragma unroll 1
    for (int kt = 0; kt < KT; kt++) {
        As[(lc4 * 4 + 0) * LDA + lr]      = pa0.x;
        As[(lc4 * 4 + 1) * LDA + lr]      = pa0.y;
        As[(lc4 * 4 + 2) * LDA + lr]      = pa0.z;
        As[(lc4 * 4 + 3) * LDA + lr]      = pa0.w;
        As[(lc4 * 4 + 0) * LDA + lr + 64] = pa1.x;
        As[(lc4 * 4 + 1) * LDA + lr + 64] = pa1.y;
        As[(lc4 * 4 + 2) * LDA + lr + 64] = pa1.z;
        As[(lc4 * 4 + 3) * LDA + lr + 64] = pa1.w;
        Ws[(lc4 * 4 + 0) * LDW + lr]      = pw0.x;
        Ws[(lc4 * 4 + 1) * LDW + lr]      = pw0.y;
        Ws[(lc4 * 4 + 2) * LDW + lr]      = pw0.z;
        Ws[(lc4 * 4 + 3) * LDW + lr]      = pw0.w;
        Ws[(lc4 * 4 + 0) * LDW + lr + 64] = pw1.x;
        Ws[(lc4 * 4 + 1) * LDW + lr + 64] = pw1.y;
        Ws[(lc4 * 4 + 2) * LDW + lr + 64] = pw1.z;
        Ws[(lc4 * 4 + 3) * LDW + lr + 64] = pw1.w;
        __syncthreads();

        if (kt + 1 < KT) {
            const float* ap = Aptr + (size_t)(kt + 1) * BK;
            const float* wp = Wptr + (size_t)(kt + 1) * BK;
            pa0 = *(const float4*)(ap);
            pa1 = *(const float4*)(ap + (size_t)64 * K);
            pw0 = *(const float4*)(wp);
            pw1 = *(const float4*)(wp + (size_t)64 * K);
        }

#pragma unroll
        for (int k = 0; k < BK; k++) {
            float4 a0 = *(const float4*)&As[k * LDA + ty * 4];
            float4 a1 = *(const float4*)&As[k * LDA + 64 + ty * 4];
            float4 w0 = *(const float4*)&Ws[k * LDW + tx * 4];
            float4 w1 = *(const float4*)&Ws[k * LDW + 64 + tx * 4];
            float av[2][4] = {{a0.x, a0.y, a0.z, a0.w}, {a1.x, a1.y, a1.z, a1.w}};
            float wv[2][4] = {{w0.x, w0.y, w0.z, w0.w}, {w1.x, w1.y, w1.z, w1.w}};
#pragma unroll
            for (int ri = 0; ri < 2; ri++)
#pragma unroll
                for (int i = 0; i < 4; i++)
#pragma unroll
                    for (int ci = 0; ci < 2; ci++)
#pragma unroll
                        for (int j = 0; j < 4; j++)
                            acc[ri][ci][i][j] += av[ri][i] * wv[ci][j];
        }
        __syncthreads();
    }

    float4 bv0 = *(const float4*)&bias[bn0 + tx * 4];
    float4 bv1 = *(const float4*)&bias[bn0 + 64 + tx * 4];
    float bb[2][4] = {{bv0.x, bv0.y, bv0.z, bv0.w}, {bv1.x, bv1.y, bv1.z, bv1.w}};

#pragma unroll
    for (int ri = 0; ri < 2; ri++)
#pragma unroll
        for (int i = 0; i < 4; i++) {
            int row = bm0 + ri * 64 + ty * 4 + i;
#pragma unroll
            for (int ci = 0; ci < 2; ci++) {
                float4 o;
                o.x = acc[ri][ci][i][0] + bb[ci][0];
                o.y = acc[ri][ci][i][1] + bb[ci][1];
                o.z = acc[ri][ci][i][2] + bb[ci][2];
                o.w = acc[ri][ci][i][3] + bb[ci][3];
                *(float4*)&C[(size_t)row * N + bn0 + ci * 64 + tx * 4] = o;
            }
        }
}

// ---------------------------------------------------------------------------
// One LSTM time step, fused (unchanged)
// ---------------------------------------------------------------------------
template<int H>
__global__ __launch_bounds__(256)
void lstm_step(const float* __restrict__ pre, const float* __restrict__ hprev,
               const float* __restrict__ Whh, const float* __restrict__ cprev,
               float* __restrict__ cout, float* __restrict__ hout)
{
    constexpr int BB = 32, GU = 8, KC = 64;
    __shared__ float hs[BB * (KC + 1)];
    __shared__ float ws[KC * 36];
    __shared__ float gsm[4 * GU * 33];

    const int tid = threadIdx.x;
    const int u0 = blockIdx.x * GU;
    const int b0 = blockIdx.y * BB;

    const int b  = tid & 31;
    const int rg = tid >> 5;

    const int fr = tid & 31;
    const int kg = tid >> 5;
    const int gate = fr >> 3;
    const int ul_f = fr & 7;
    const float* wrow = Whh + (size_t)(gate * H + u0 + ul_f) * H;
    const float* hrow = hprev + (size_t)(b0 + fr) * H;

    float a0 = 0.f, a1 = 0.f, a2 = 0.f, a3 = 0.f;

    for (int k0 = 0; k0 < H; k0 += KC) {
        __syncthreads();
        {
            float4 wa = *(const float4*)(wrow + k0 + kg * 8);
            float4 wb = *(const float4*)(wrow + k0 + kg * 8 + 4);
            ws[(kg * 8 + 0) * 36 + fr] = wa.x;
            ws[(kg * 8 + 1) * 36 + fr] = wa.y;
            ws[(kg * 8 + 2) * 36 + fr] = wa.z;
            ws[(kg * 8 + 3) * 36 + fr] = wa.w;
            ws[(kg * 8 + 4) * 36 + fr] = wb.x;
            ws[(kg * 8 + 5) * 36 + fr] = wb.y;
            ws[(kg * 8 + 6) * 36 + fr] = wb.z;
            ws[(kg * 8 + 7) * 36 + fr] = wb.w;
            float4 ha = *(const float4*)(hrow + k0 + kg * 8);
            float4 hb = *(const float4*)(hrow + k0 + kg * 8 + 4);
            hs[fr * (KC + 1) + kg * 8 + 0] = ha.x;
            hs[fr * (KC + 1) + kg * 8 + 1] = ha.y;
            hs[fr * (KC + 1) + kg * 8 + 2] = ha.z;
            hs[fr * (KC + 1) + kg * 8 + 3] = ha.w;
            hs[fr * (KC + 1) + kg * 8 + 4] = hb.x;
            hs[fr * (KC + 1) + kg * 8 + 5] = hb.y;
            hs[fr * (KC + 1) + kg * 8 + 6] = hb.z;
            hs[fr * (KC + 1) + kg * 8 + 7] = hb.w;
        }
        __syncthreads();
#pragma unroll
        for (int kk = 0; kk < KC; kk++) {
            float hv = hs[b * (KC + 1) + kk];
            float4 wv = *(const float4*)&ws[kk * 36 + rg * 4];
            a0 += hv * wv.x;
            a1 += hv * wv.y;
            a2 += hv * wv.z;
            a3 += hv * wv.w;
        }
    }

    gsm[(rg * 4 + 0) * 33 + b] = a0;
    gsm[(rg * 4 + 1) * 33 + b] = a1;
    gsm[(rg * 4 + 2) * 33 + b] = a2;
    gsm[(rg * 4 + 3) * 33 + b] = a3;
    __syncthreads();

    const int bb2 = tid & 31;
    const int ul  = tid >> 5;
    const float* prow = pre + (size_t)(b0 + bb2) * 4 * H + u0 + ul;
    float gi = prow[0]     + gsm[(0 * GU + ul) * 33 + bb2];
    float gf = prow[H]     + gsm[(1 * GU + ul) * 33 + bb2];
    float gg = prow[2 * H] + gsm[(2 * GU + ul) * 33 + bb2];
    float go = prow[3 * H] + gsm[(3 * GU + ul) * 33 + bb2];

    float si = 1.f / (1.f + __expf(-gi));
    float sf = 1.f / (1.f + __expf(-gf));
    float so = 1.f / (1.f + __expf(-go));
    float tg = tanhf(gg);

    const int ci = (b0 + bb2) * H + u0 + ul;
    float cn = sf * cprev[ci] + si * tg;
    cout[ci] = cn;
    hout[ci] = so * tanhf(cn);
}

// ---------------------------------------------------------------------------
extern "C" void kernel_launch(void* const* d_in, const int* in_sizes, int n_in,
                              void* d_out, int out_size)
{
    const float* inp  = (const float*)d_in[0];
    const float* Wih1 = (const float*)d_in[1];
    const float* Whh1 = (const float*)d_in[2];
    const float* b1   = (const float*)d_in[3];
    const float* Wih2 = (const float*)d_in[4];
    const float* Whh2 = (const float*)d_in[5];
    const float* b2   = (const float*)d_in[6];
    float* out = (float*)d_out;

    float *pre1, *y1, *c1, *pre2, *c2, *zero;
    cudaGetSymbolAddress((void**)&pre1, g_pre1);
    cudaGetSymbolAddress((void**)&y1,   g_y1);
    cudaGetSymbolAddress((void**)&c1,   g_c1);
    cudaGetSymbolAddress((void**)&pre2, g_pre2);
    cudaGetSymbolAddress((void**)&c2,   g_c2);
    cudaGetSymbolAddress((void**)&zero, g_zero);

    __nv_bfloat16 *ahi, *alo, *whi, *wlo;
    cudaGetSymbolAddress((void**)&ahi, g_Ahi);
    cudaGetSymbolAddress((void**)&alo, g_Alo);
    cudaGetSymbolAddress((void**)&whi, g_Whi);
    cudaGetSymbolAddress((void**)&wlo, g_Wlo);

    cudaFuncSetAttribute(gemm_mma_split,
                         cudaFuncAttributeMaxDynamicSharedMemorySize, GEMM_SMEM);

    const int M = T_STEPS * BATCH;  // 2048

    // split inputs and layer-1 weights into (hi, lo) bf16
    {
        int n4a = M * IN_DIM / 4;
        split_bf16<<<(n4a + 255) / 256, 256>>>(inp, ahi, alo, n4a);
        int n4w = 4 * HH1 * IN_DIM / 4;
        split_bf16<<<(n4w + 255) / 256, 256>>>(Wih1, whi, wlo, n4w);
    }

    // Layer 1 input projection on tensor cores (mma.sync): pre1 = X @ Wih1^T + b1
    gemm_mma_split<<<dim3(4 * HH1 / 128, M / 128), 256, GEMM_SMEM>>>(
        ahi, alo, whi, wlo, b1, pre1, 4 * HH1, IN_DIM);

    // Layer 1 recurrence
    for (int t = 0; t < T_STEPS; t++) {
        const float* hp = (t == 0) ? zero : (y1 + (size_t)(t - 1) * BATCH * HH1);
        const float* cp = (t == 0) ? zero : c1;
        lstm_step<HH1><<<dim3(HH1 / 8, BATCH / 32), 256>>>(
            pre1 + (size_t)t * BATCH * 4 * HH1, hp, Whh1, cp, c1,
            y1 + (size_t)t * BATCH * HH1);
    }

    // Layer 2 input projection (small, K=256): fp32 SGEMM
    sgemm_nt_bias<128, 128, 16>
        <<<dim3(4 * HH2 / 128, M / 128), 256>>>(y1, Wih2, b2, pre2, M, 4 * HH2, HH1);

    // Layer 2 recurrence (h written straight into d_out)
    for (int t = 0; t < T_STEPS; t++) {
        const float* hp = (t == 0) ? zero : (out + (size_t)(t - 1) * BATCH * HH2);
        const float* cp = (t == 0) ? zero : c2;
        lstm_step<HH2><<<dim3(HH2 / 8, BATCH / 32), 256>>>(
            pre2 + (size_t)t * BATCH * 4 * HH2, hp, Whh2, cp, c2,
            out + (size_t)t * BATCH * HH2);
    }
}

// round 7
// speedup vs baseline: 2.1325x; 1.2577x over previous
#include <cuda_runtime.h>
#include <cuda_bf16.h>
#include <cstdint>
#include <math.h>

#define T_STEPS 16
#define BATCH   128
#define IN_DIM  12288
#define HH1     256
#define HH2     512

// ---------------- scratch (static __device__ globals; no runtime alloc) ----
__device__ float g_pre1[T_STEPS * BATCH * 4 * HH1];   //  8.4 MB
__device__ float g_y1  [T_STEPS * BATCH * HH1];       //  2.1 MB
__device__ float g_pre2[T_STEPS * BATCH * 4 * HH2];   // 16.8 MB

// split-bf16 staging for the big layer-1 GEMM
__device__ __nv_bfloat16 g_Ahi[T_STEPS * BATCH * IN_DIM];   // 50 MB
__device__ __nv_bfloat16 g_Alo[T_STEPS * BATCH * IN_DIM];   // 50 MB
__device__ __nv_bfloat16 g_Whi[4 * HH1 * IN_DIM];           // 25 MB
__device__ __nv_bfloat16 g_Wlo[4 * HH1 * IN_DIM];           // 25 MB

// grid-wide barrier state (monotone generation; count self-resets)
__device__ unsigned g_bar_count = 0;
__device__ unsigned g_bar_gen   = 0;

// ===========================================================================
// helpers
// ===========================================================================
__device__ __forceinline__ uint32_t smem_u32(const void* p) {
    uint32_t a;
    asm("{ .reg .u64 t; cvta.to.shared.u64 t, %1; cvt.u32.u64 %0, t; }"
        : "=r"(a) : "l"(p));
    return a;
}

#define LDSM_X4(r, addr) \
    asm volatile("ldmatrix.sync.aligned.m8n8.x4.shared.b16 {%0,%1,%2,%3}, [%4];" \
        : "=r"((r)[0]), "=r"((r)[1]), "=r"((r)[2]), "=r"((r)[3]) : "r"(addr))

#define MMA16816(d, a, b0v, b1v) \
    asm volatile("mma.sync.aligned.m16n8k16.row.col.f32.bf16.bf16.f32 " \
        "{%0,%1,%2,%3}, {%4,%5,%6,%7}, {%8,%9}, {%0,%1,%2,%3};" \
        : "+f"((d)[0]), "+f"((d)[1]), "+f"((d)[2]), "+f"((d)[3]) \
        : "r"((a)[0]), "r"((a)[1]), "r"((a)[2]), "r"((a)[3]), \
          "r"(b0v), "r"(b1v))

#define CP_ASYNC16(dst, src) \
    asm volatile("cp.async.cg.shared.global [%0], [%1], 16;" \
        :: "r"(dst), "l"(src))
#define CP_COMMIT() asm volatile("cp.async.commit_group;" ::: "memory")
#define CP_WAIT0()  asm volatile("cp.async.wait_group 0;"  ::: "memory")
#define CP_WAIT1()  asm volatile("cp.async.wait_group 1;"  ::: "memory")
#define CP_WAIT2()  asm volatile("cp.async.wait_group 2;"  ::: "memory")

// device-wide barrier: all nblocks must be co-resident (1 block/SM here).
__device__ __forceinline__ void grid_sync_dev(unsigned& lgen, int nblocks) {
    __syncthreads();
    if (threadIdx.x == 0) {
        __threadfence();
        unsigned a = atomicAdd(&g_bar_count, 1);
        if (a == (unsigned)(nblocks - 1)) {
            g_bar_count = 0;
            __threadfence();
            atomicAdd(&g_bar_gen, 1);
        } else {
            while (*(volatile unsigned*)&g_bar_gen <= lgen) { }
            __threadfence();
        }
        lgen++;
    }
    __syncthreads();
}

// ===========================================================================
// fp32 -> (hi, lo) bf16 split
// ===========================================================================
__global__ __launch_bounds__(256)
void split_bf16(const float* __restrict__ x, __nv_bfloat16* __restrict__ hi,
                __nv_bfloat16* __restrict__ lo, int n4) {
    int i = blockIdx.x * blockDim.x + threadIdx.x;
    if (i >= n4) return;
    float4 v = ((const float4*)x)[i];
    float vv[4] = {v.x, v.y, v.z, v.w};
    __align__(8) __nv_bfloat16 h[4], l[4];
#pragma unroll
    for (int j = 0; j < 4; j++) {
        h[j] = __float2bfloat16(vv[j]);
        l[j] = __float2bfloat16(vv[j] - __bfloat162float(h[j]));
    }
    ((uint2*)hi)[i] = *(uint2*)h;
    ((uint2*)lo)[i] = *(uint2*)l;
}

// ===========================================================================
// split-bf16 GEMM on mma.sync:  C[M,N] = A[M,K] @ W[N,K]^T + bias[N]
// 128x128 CTA tile, BK=64 (128B rows, XOR-8 swizzle), 3-stage cp.async.
// ===========================================================================
#define MT_BYTES   16384                 // one 128x64 bf16 tile
#define STAGE_B    (4 * MT_BYTES)        // Ahi, Alo, Whi, Wlo
#define GEMM_SMEM  (3 * STAGE_B)         // 192 KB

__global__ __launch_bounds__(256, 1)
void gemm_mma_split(const __nv_bfloat16* __restrict__ Ahi,
                    const __nv_bfloat16* __restrict__ Alo,
                    const __nv_bfloat16* __restrict__ Whi,
                    const __nv_bfloat16* __restrict__ Wlo,
                    const float* __restrict__ bias,
                    float* __restrict__ C,
                    int N, int K)
{
    extern __shared__ __align__(1024) char smem[];
    const uint32_t sb = smem_u32(smem);

    const int tid  = threadIdx.x;
    const int lane = tid & 31;
    const int wid  = tid >> 5;
    const int warp_m = wid & 3;
    const int warp_n = wid >> 2;
    const int bm0 = blockIdx.y * 128;
    const int bn0 = blockIdx.x * 128;

    const int lr = tid >> 3;             // 0..31
    const int lc = tid & 7;              // 0..7

    const __nv_bfloat16* srcA[2] = { Ahi + (size_t)bm0 * K,  Alo + (size_t)bm0 * K };
    const __nv_bfloat16* srcW[2] = { Whi + (size_t)bn0 * K,  Wlo + (size_t)bn0 * K };

    const int NC = K / 64;

    auto issue_stage = [&](int kc, int stage) {
        const size_t koff = (size_t)kc * 64;
        const uint32_t stb = sb + stage * STAGE_B;
#pragma unroll
        for (int t = 0; t < 4; t++) {
            const __nv_bfloat16* base = (t < 2) ? srcA[t] : srcW[t - 2];
            const uint32_t tb = stb + t * MT_BYTES;
#pragma unroll
            for (int i = 0; i < 4; i++) {
                int rr = lr + i * 32;
                const __nv_bfloat16* src = base + (size_t)rr * K + koff + lc * 8;
                uint32_t dst = tb + rr * 128 + ((lc ^ (rr & 7)) * 16);
                CP_ASYNC16(dst, src);
            }
        }
    };

    float acc[2][8][4];
#pragma unroll
    for (int mt = 0; mt < 2; mt++)
#pragma unroll
        for (int nt = 0; nt < 8; nt++)
#pragma unroll
            for (int j = 0; j < 4; j++)
                acc[mt][nt][j] = 0.f;

    const int arow  = warp_m * 32 + (lane & 15);
    const int ahalf = lane >> 4;
    const int brow  = warp_n * 64 + ((lane >> 4) << 3) + (lane & 7);
    const int bhalf = (lane >> 3) & 1;

    issue_stage(0, 0); CP_COMMIT();
    issue_stage(1, 1); CP_COMMIT();

#pragma unroll 1
    for (int kc = 0; kc < NC; kc++) {
        if (kc + 2 < NC) issue_stage(kc + 2, (kc + 2) % 3);
        CP_COMMIT();
        CP_WAIT2();
        __syncthreads();

        const uint32_t stb = sb + (kc % 3) * STAGE_B;
        const uint32_t tAh = stb;
        const uint32_t tAl = stb + MT_BYTES;
        const uint32_t tWh = stb + 2 * MT_BYTES;
        const uint32_t tWl = stb + 3 * MT_BYTES;

#pragma unroll
        for (int ks = 0; ks < 4; ks++) {
            uint32_t ahi[2][4], alo[2][4], bhi[4][4], blo[4][4];
#pragma unroll
            for (int mt = 0; mt < 2; mt++) {
                int r  = arow + mt * 16;
                int ch = 2 * ks + ahalf;
                uint32_t off = r * 128 + ((ch ^ (r & 7)) * 16);
                LDSM_X4(ahi[mt], tAh + off);
                LDSM_X4(alo[mt], tAl + off);
            }
#pragma unroll
            for (int nt2 = 0; nt2 < 4; nt2++) {
                int r  = brow + nt2 * 16;
                int ch = 2 * ks + bhalf;
                uint32_t off = r * 128 + ((ch ^ (r & 7)) * 16);
                LDSM_X4(bhi[nt2], tWh + off);
                LDSM_X4(blo[nt2], tWl + off);
            }
#pragma unroll
            for (int mt = 0; mt < 2; mt++)
#pragma unroll
                for (int nt = 0; nt < 8; nt++) {
                    const uint32_t* bh = &bhi[nt >> 1][(nt & 1) * 2];
                    const uint32_t* bl = &blo[nt >> 1][(nt & 1) * 2];
                    MMA16816(acc[mt][nt], ahi[mt], bh[0], bh[1]);
                    MMA16816(acc[mt][nt], ahi[mt], bl[0], bl[1]);
                    MMA16816(acc[mt][nt], alo[mt], bh[0], bh[1]);
                }
        }
        __syncthreads();
    }

#pragma unroll
    for (int mt = 0; mt < 2; mt++) {
        int row0 = bm0 + warp_m * 32 + mt * 16 + (lane >> 2);
#pragma unroll
        for (int nt = 0; nt < 8; nt++) {
            int col = bn0 + warp_n * 64 + nt * 8 + (lane & 3) * 2;
            float b0 = bias[col], b1 = bias[col + 1];
            float2 o0 = { acc[mt][nt][0] + b0, acc[mt][nt][1] + b1 };
            float2 o1 = { acc[mt][nt][2] + b0, acc[mt][nt][3] + b1 };
            *(float2*)&C[(size_t)row0 * N + col]       = o0;
            *(float2*)&C[(size_t)(row0 + 8) * N + col] = o1;
        }
    }
}

// ---------------------------------------------------------------------------
// fp32 SGEMM (layer-2 input projection, K=256)
// ---------------------------------------------------------------------------
template<int BM, int BN, int BK>
__global__ __launch_bounds__(256)
void sgemm_nt_bias(const float* __restrict__ A, const float* __restrict__ W,
                   const float* __restrict__ bias, float* __restrict__ C,
                   int M, int N, int K)
{
    constexpr int LDA = BM + 4;
    constexpr int LDW = BN + 4;
    __shared__ float As[BK * LDA];
    __shared__ float Ws[BK * LDW];

    const int tid = threadIdx.x;
    const int tx  = tid & 15;
    const int ty  = tid >> 4;
    const int lr  = tid >> 2;
    const int lc4 = tid & 3;
    const int bm0 = blockIdx.y * BM;
    const int bn0 = blockIdx.x * BN;

    const float* Aptr = A + (size_t)(bm0 + lr) * K + lc4 * 4;
    const float* Wptr = W + (size_t)(bn0 + lr) * K + lc4 * 4;

    float acc[2][2][4][4];
#pragma unroll
    for (int ri = 0; ri < 2; ri++)
#pragma unroll
        for (int ci = 0; ci < 2; ci++)
#pragma unroll
            for (int i = 0; i < 4; i++)
#pragma unroll
                for (int j = 0; j < 4; j++)
                    acc[ri][ci][i][j] = 0.f;

    const int KT = K / BK;
    float4 pa0 = *(const float4*)(Aptr);
    float4 pa1 = *(const float4*)(Aptr + (size_t)64 * K);
    float4 pw0 = *(const float4*)(Wptr);
    float4 pw1 = *(const float4*)(Wptr + (size_t)64 * K);

#pragma unroll 1
    for (int kt = 0; kt < KT; kt++) {
        As[(lc4 * 4 + 0) * LDA + lr]      = pa0.x;
        As[(lc4 * 4 + 1) * LDA + lr]      = pa0.y;
        As[(lc4 * 4 + 2) * LDA + lr]      = pa0.z;
        As[(lc4 * 4 + 3) * LDA + lr]      = pa0.w;
        As[(lc4 * 4 + 0) * LDA + lr + 64] = pa1.x;
        As[(lc4 * 4 + 1) * LDA + lr + 64] = pa1.y;
        As[(lc4 * 4 + 2) * LDA + lr + 64] = pa1.z;
        As[(lc4 * 4 + 3) * LDA + lr + 64] = pa1.w;
        Ws[(lc4 * 4 + 0) * LDW + lr]      = pw0.x;
        Ws[(lc4 * 4 + 1) * LDW + lr]      = pw0.y;
        Ws[(lc4 * 4 + 2) * LDW + lr]      = pw0.z;
        Ws[(lc4 * 4 + 3) * LDW + lr]      = pw0.w;
        Ws[(lc4 * 4 + 0) * LDW + lr + 64] = pw1.x;
        Ws[(lc4 * 4 + 1) * LDW + lr + 64] = pw1.y;
        Ws[(lc4 * 4 + 2) * LDW + lr + 64] = pw1.z;
        Ws[(lc4 * 4 + 3) * LDW + lr + 64] = pw1.w;
        __syncthreads();

        if (kt + 1 < KT) {
            const float* ap = Aptr + (size_t)(kt + 1) * BK;
            const float* wp = Wptr + (size_t)(kt + 1) * BK;
            pa0 = *(const float4*)(ap);
            pa1 = *(const float4*)(ap + (size_t)64 * K);
            pw0 = *(const float4*)(wp);
            pw1 = *(const float4*)(wp + (size_t)64 * K);
        }

#pragma unroll
        for (int k = 0; k < BK; k++) {
            float4 a0 = *(const float4*)&As[k * LDA + ty * 4];
            float4 a1 = *(const float4*)&As[k * LDA + 64 + ty * 4];
            float4 w0 = *(const float4*)&Ws[k * LDW + tx * 4];
            float4 w1 = *(const float4*)&Ws[k * LDW + 64 + tx * 4];
            float av[2][4] = {{a0.x, a0.y, a0.z, a0.w}, {a1.x, a1.y, a1.z, a1.w}};
            float wv[2][4] = {{w0.x, w0.y, w0.z, w0.w}, {w1.x, w1.y, w1.z, w1.w}};
#pragma unroll
            for (int ri = 0; ri < 2; ri++)
#pragma unroll
                for (int i = 0; i < 4; i++)
#pragma unroll
                    for (int ci = 0; ci < 2; ci++)
#pragma unroll
                        for (int j = 0; j < 4; j++)
                            acc[ri][ci][i][j] += av[ri][i] * wv[ci][j];
        }
        __syncthreads();
    }

    float4 bv0 = *(const float4*)&bias[bn0 + tx * 4];
    float4 bv1 = *(const float4*)&bias[bn0 + 64 + tx * 4];
    float bb[2][4] = {{bv0.x, bv0.y, bv0.z, bv0.w}, {bv1.x, bv1.y, bv1.z, bv1.w}};

#pragma unroll
    for (int ri = 0; ri < 2; ri++)
#pragma unroll
        for (int i = 0; i < 4; i++) {
            int row = bm0 + ri * 64 + ty * 4 + i;
#pragma unroll
            for (int ci = 0; ci < 2; ci++) {
                float4 o;
                o.x = acc[ri][ci][i][0] + bb[ci][0];
                o.y = acc[ri][ci][i][1] + bb[ci][1];
                o.z = acc[ri][ci][i][2] + bb[ci][2];
                o.w = acc[ri][ci][i][3] + bb[ci][3];
                *(float4*)&C[(size_t)row * N + bn0 + ci * 64 + tx * 4] = o;
            }
        }
}

// ===========================================================================
// Persistent layer-1 recurrence: 128 blocks x 256 threads, all 16 steps.
// Block owns 2 units (8 gate rows). Weights stationary in smem.
// Thread owns one (b, u) cell; c lives in a register.
// ===========================================================================
#define REC1_SMEM ((8 * 256 + 128 * 260) * 4)   // 138 KB

__global__ __launch_bounds__(256, 1)
void lstm_rec1(const float* __restrict__ pre,   // [16][128][1024]
               const float* __restrict__ Whh,   // [1024][256]
               float* __restrict__ y1)          // [16][128][256]
{
    extern __shared__ float sm1[];
    float* ws = sm1;                 // [8][256]
    float* hs = sm1 + 8 * 256;       // [128][260] (pad 4)
    const uint32_t hs_b = smem_u32(hs);

    const int tid = threadIdx.x;
    const int bk  = blockIdx.x;
    const int u0  = bk * 2;
    const int b   = tid & 127;
    const int uu  = tid >> 7;        // 0..1
    const int u   = u0 + uu;

    for (int i = tid; i < 8 * 256; i += 256) {
        int lr = i >> 8, k = i & 255;
        int g = lr >> 1, j = lr & 1;
        ws[lr * 256 + k] = Whh[(size_t)(g * HH1 + u0 + j) * HH1 + k];
    }
    unsigned lgen = 0;
    if (tid == 0) lgen = *(volatile unsigned*)&g_bar_gen;
    __syncthreads();

    const float4* ws4 = (const float4*)ws;
    const float4* w0 = ws4 + (0 + uu) * 64;
    const float4* w1 = ws4 + (2 + uu) * 64;
    const float4* w2 = ws4 + (4 + uu) * 64;
    const float4* w3 = ws4 + (6 + uu) * 64;

    float c = 0.f;

#pragma unroll 1
    for (int t = 0; t < T_STEPS; t++) {
        float a0 = 0.f, a1 = 0.f, a2 = 0.f, a3 = 0.f;
        if (t > 0) {
            const float* hsrc = y1 + (size_t)(t - 1) * BATCH * HH1;
#pragma unroll
            for (int i = 0; i < 32; i++) {
                int flat = tid + i * 256;        // 8192 float4 total
                int row = flat >> 6;
                int c16 = flat & 63;
                CP_ASYNC16(hs_b + row * 1040 + c16 * 16,
                           hsrc + row * HH1 + c16 * 4);
            }
            CP_COMMIT(); CP_WAIT0();
            __syncthreads();

            const float4* h4 = (const float4*)(hs + b * 260);
#pragma unroll 8
            for (int k4 = 0; k4 < 64; k4++) {
                float4 hv = h4[k4];
                float4 wa = w0[k4], wb = w1[k4], wc = w2[k4], wd = w3[k4];
                a0 += hv.x * wa.x + hv.y * wa.y + hv.z * wa.z + hv.w * wa.w;
                a1 += hv.x * wb.x + hv.y * wb.y + hv.z * wb.z + hv.w * wb.w;
                a2 += hv.x * wc.x + hv.y * wc.y + hv.z * wc.z + hv.w * wc.w;
                a3 += hv.x * wd.x + hv.y * wd.y + hv.z * wd.z + hv.w * wd.w;
            }
        }
        const float* prow = pre + ((size_t)t * BATCH + b) * (4 * HH1) + u;
        float gi = prow[0]       + a0;
        float gf = prow[HH1]     + a1;
        float gg = prow[2 * HH1] + a2;
        float go = prow[3 * HH1] + a3;

        float si = 1.f / (1.f + __expf(-gi));
        float sf = 1.f / (1.f + __expf(-gf));
        float so = 1.f / (1.f + __expf(-go));
        float tg = tanhf(gg);
        c = sf * c + si * tg;
        y1[((size_t)t * BATCH + b) * HH1 + u] = so * tanhf(c);

        if (t < T_STEPS - 1) grid_sync_dev(lgen, 128);
        else __syncthreads();
    }
}

// ===========================================================================
// Persistent layer-2 recurrence: 128 blocks x 256 threads, all 16 steps.
// Block owns 4 units (16 gate rows, 32 KB weights in smem).
// Thread owns two (b, u) cells. h staged in 2x(128x132) double buffer.
// ===========================================================================
#define REC2_SMEM ((16 * 512 + 2 * 128 * 132) * 4)   // 164 KB

__global__ __launch_bounds__(256, 1)
void lstm_rec2(const float* __restrict__ pre,   // [16][128][2048]
               const float* __restrict__ Whh,   // [2048][512]
               float* __restrict__ out)         // [16][128][512]
{
    extern __shared__ float sm2[];
    float* ws = sm2;                    // [16][512]
    float* hs = sm2 + 16 * 512;         // 2 x [128][132]
    const uint32_t hs_b = smem_u32(hs);

    const int tid = threadIdx.x;
    const int bk  = blockIdx.x;
    const int u0  = bk * 4;
    const int b   = tid & 127;
    const int uh  = tid >> 7;           // 0..1 -> units uh, uh+2

    for (int i = tid; i < 16 * 512; i += 256) {
        int lr = i >> 9, k = i & 511;
        int g = lr >> 2, j = lr & 3;
        ws[lr * 512 + k] = Whh[(size_t)(g * HH2 + u0 + j) * HH2 + k];
    }
    unsigned lgen = 0;
    if (tid == 0) lgen = *(volatile unsigned*)&g_bar_gen;
    __syncthreads();

    const float4* ws4 = (const float4*)ws;   // [16][128]
    float c0 = 0.f, c1 = 0.f;

#pragma unroll 1
    for (int t = 0; t < T_STEPS; t++) {
        float acc[8];
#pragma unroll
        for (int i = 0; i < 8; i++) acc[i] = 0.f;

        if (t > 0) {
            const float* hsrc = out + (size_t)(t - 1) * BATCH * HH2;

            auto issue_chunk = [&](int kc, int buf) {
#pragma unroll
                for (int i = 0; i < 16; i++) {
                    int flat = tid + i * 256;        // 4096 float4
                    int row = flat >> 5;
                    int c16 = flat & 31;
                    CP_ASYNC16(hs_b + buf * (128 * 132 * 4) + row * 528 + c16 * 16,
                               hsrc + row * HH2 + kc * 128 + c16 * 4);
                }
            };

            issue_chunk(0, 0); CP_COMMIT();
#pragma unroll 1
            for (int kc = 0; kc < 4; kc++) {
                if (kc + 1 < 4) issue_chunk(kc + 1, (kc + 1) & 1);
                CP_COMMIT();
                CP_WAIT1();
                __syncthreads();

                const float4* h4 = (const float4*)(hs + (kc & 1) * (128 * 132) + b * 132);
#pragma unroll 4
                for (int k4 = 0; k4 < 32; k4++) {
                    float4 hv = h4[k4];
#pragma unroll
                    for (int g = 0; g < 4; g++) {
#pragma unroll
                        for (int uj = 0; uj < 2; uj++) {
                            float4 wv = ws4[(g * 4 + uh + uj * 2) * 128 + kc * 32 + k4];
                            acc[g * 2 + uj] += hv.x * wv.x + hv.y * wv.y +
                                               hv.z * wv.z + hv.w * wv.w;
                        }
                    }
                }
                __syncthreads();
            }
        }

        const float* prow = pre + ((size_t)t * BATCH + b) * (4 * HH2);
#pragma unroll
        for (int uj = 0; uj < 2; uj++) {
            int u = u0 + uh + uj * 2;
            float gi = prow[0 * HH2 + u] + acc[0 + uj];
            float gf = prow[1 * HH2 + u] + acc[2 + uj];
            float gg = prow[2 * HH2 + u] + acc[4 + uj];
            float go = prow[3 * HH2 + u] + acc[6 + uj];

            float si = 1.f / (1.f + __expf(-gi));
            float sf = 1.f / (1.f + __expf(-gf));
            float so = 1.f / (1.f + __expf(-go));
            float tg = tanhf(gg);
            float& cc = uj ? c1 : c0;
            cc = sf * cc + si * tg;
            out[((size_t)t * BATCH + b) * HH2 + u] = so * tanhf(cc);
        }

        if (t < T_STEPS - 1) grid_sync_dev(lgen, 128);
        else __syncthreads();
    }
}

// ---------------------------------------------------------------------------
extern "C" void kernel_launch(void* const* d_in, const int* in_sizes, int n_in,
                              void* d_out, int out_size)
{
    const float* inp  = (const float*)d_in[0];
    const float* Wih1 = (const float*)d_in[1];
    const float* Whh1 = (const float*)d_in[2];
    const float* b1   = (const float*)d_in[3];
    const float* Wih2 = (const float*)d_in[4];
    const float* Whh2 = (const float*)d_in[5];
    const float* b2   = (const float*)d_in[6];
    float* out = (float*)d_out;

    float *pre1, *y1, *pre2;
    cudaGetSymbolAddress((void**)&pre1, g_pre1);
    cudaGetSymbolAddress((void**)&y1,   g_y1);
    cudaGetSymbolAddress((void**)&pre2, g_pre2);

    __nv_bfloat16 *ahi, *alo, *whi, *wlo;
    cudaGetSymbolAddress((void**)&ahi, g_Ahi);
    cudaGetSymbolAddress((void**)&alo, g_Alo);
    cudaGetSymbolAddress((void**)&whi, g_Whi);
    cudaGetSymbolAddress((void**)&wlo, g_Wlo);

    cudaFuncSetAttribute(gemm_mma_split,
                         cudaFuncAttributeMaxDynamicSharedMemorySize, GEMM_SMEM);
    cudaFuncSetAttribute(lstm_rec1,
                         cudaFuncAttributeMaxDynamicSharedMemorySize, REC1_SMEM);
    cudaFuncSetAttribute(lstm_rec2,
                         cudaFuncAttributeMaxDynamicSharedMemorySize, REC2_SMEM);

    const int M = T_STEPS * BATCH;  // 2048

    // split inputs and layer-1 weights into (hi, lo) bf16
    {
        int n4a = M * IN_DIM / 4;
        split_bf16<<<(n4a + 255) / 256, 256>>>(inp, ahi, alo, n4a);
        int n4w = 4 * HH1 * IN_DIM / 4;
        split_bf16<<<(n4w + 255) / 256, 256>>>(Wih1, whi, wlo, n4w);
    }

    // Layer 1 input projection (tensor cores): pre1 = X @ Wih1^T + b1
    gemm_mma_split<<<dim3(4 * HH1 / 128, M / 128), 256, GEMM_SMEM>>>(
        ahi, alo, whi, wlo, b1, pre1, 4 * HH1, IN_DIM);

    // Layer 1 recurrence: one persistent kernel, 16 steps
    lstm_rec1<<<128, 256, REC1_SMEM>>>(pre1, Whh1, y1);

    // Layer 2 input projection (K=256): fp32 SGEMM
    sgemm_nt_bias<128, 128, 16>
        <<<dim3(4 * HH2 / 128, M / 128), 256>>>(y1, Wih2, b2, pre2, M, 4 * HH2, HH1);

    // Layer 2 recurrence: one persistent kernel, h written straight into d_out
    lstm_rec2<<<128, 256, REC2_SMEM>>>(pre2, Whh2, out);
}

// round 8
// speedup vs baseline: 2.3402x; 1.0974x over previous
#include <cuda_runtime.h>
#include <cuda_bf16.h>
#include <cstdint>
#include <math.h>

#define T_STEPS 16
#define BATCH   128
#define IN_DIM  12288
#define HH1     256
#define HH2     512

// ---------------- scratch (static __device__ globals; no runtime alloc) ----
__device__ float g_pre1[T_STEPS * BATCH * 4 * HH1];   //  8.4 MB
__device__ float g_y1  [T_STEPS * BATCH * HH1];       //  2.1 MB
__device__ float g_pre2[T_STEPS * BATCH * 4 * HH2];   // 16.8 MB

// split-bf16 staging
__device__ __nv_bfloat16 g_Ahi[T_STEPS * BATCH * IN_DIM];   // 50 MB
__device__ __nv_bfloat16 g_Alo[T_STEPS * BATCH * IN_DIM];   // 50 MB
__device__ __nv_bfloat16 g_Whi[4 * HH1 * IN_DIM];           // 25 MB
__device__ __nv_bfloat16 g_Wlo[4 * HH1 * IN_DIM];           // 25 MB
__device__ __nv_bfloat16 g_Y1hi[T_STEPS * BATCH * HH1];     //  1 MB
__device__ __nv_bfloat16 g_Y1lo[T_STEPS * BATCH * HH1];     //  1 MB
__device__ __nv_bfloat16 g_W2hi[4 * HH2 * HH1];             //  1 MB
__device__ __nv_bfloat16 g_W2lo[4 * HH2 * HH1];             //  1 MB

// quarter-local barrier state (stride 32 u32 = 128 B to avoid false sharing)
__device__ unsigned g_bcnt[4 * 32];
__device__ unsigned g_bgen[4 * 32];

// ===========================================================================
// helpers
// ===========================================================================
__device__ __forceinline__ uint32_t smem_u32(const void* p) {
    uint32_t a;
    asm("{ .reg .u64 t; cvta.to.shared.u64 t, %1; cvt.u32.u64 %0, t; }"
        : "=r"(a) : "l"(p));
    return a;
}

#define LDSM_X4(r, addr) \
    asm volatile("ldmatrix.sync.aligned.m8n8.x4.shared.b16 {%0,%1,%2,%3}, [%4];" \
        : "=r"((r)[0]), "=r"((r)[1]), "=r"((r)[2]), "=r"((r)[3]) : "r"(addr))

#define MMA16816(d, a, b0v, b1v) \
    asm volatile("mma.sync.aligned.m16n8k16.row.col.f32.bf16.bf16.f32 " \
        "{%0,%1,%2,%3}, {%4,%5,%6,%7}, {%8,%9}, {%0,%1,%2,%3};" \
        : "+f"((d)[0]), "+f"((d)[1]), "+f"((d)[2]), "+f"((d)[3]) \
        : "r"((a)[0]), "r"((a)[1]), "r"((a)[2]), "r"((a)[3]), \
          "r"(b0v), "r"(b1v))

#define CP_ASYNC16(dst, src) \
    asm volatile("cp.async.cg.shared.global [%0], [%1], 16;" \
        :: "r"(dst), "l"(src))
#define CP_COMMIT() asm volatile("cp.async.commit_group;" ::: "memory")
#define CP_WAIT0()  asm volatile("cp.async.wait_group 0;"  ::: "memory")
#define CP_WAIT2()  asm volatile("cp.async.wait_group 2;"  ::: "memory")

// packed dual-FMA: d.lo += a.lo*b.lo ; d.hi += a.hi*b.hi  (Blackwell f32x2)
#define FMA_F32X2(d, a, b) \
    asm("fma.rn.f32x2 %0, %1, %2, %0;" : "+l"(d) : "l"(a), "l"(b))

__device__ __forceinline__ float unpack_sum(unsigned long long v) {
    return __uint_as_float((unsigned)(v & 0xffffffffull)) +
           __uint_as_float((unsigned)(v >> 32));
}

// quarter-local device barrier over nblocks co-resident blocks
__device__ __forceinline__ void grid_sync_q(unsigned& lgen, unsigned* cnt,
                                            unsigned* gen, int nblocks) {
    __syncthreads();
    if (threadIdx.x == 0) {
        __threadfence();
        unsigned a = atomicAdd(cnt, 1);
        if (a == (unsigned)(nblocks - 1)) {
            *cnt = 0;
            __threadfence();
            atomicAdd(gen, 1);
        } else {
            while (*(volatile unsigned*)gen <= lgen) { }
            __threadfence();
        }
        lgen++;
    }
    __syncthreads();
}

// ===========================================================================
// fp32 -> (hi, lo) bf16 split
// ===========================================================================
__global__ __launch_bounds__(256)
void split_bf16(const float* __restrict__ x, __nv_bfloat16* __restrict__ hi,
                __nv_bfloat16* __restrict__ lo, int n4) {
    int i = blockIdx.x * blockDim.x + threadIdx.x;
    if (i >= n4) return;
    float4 v = ((const float4*)x)[i];
    float vv[4] = {v.x, v.y, v.z, v.w};
    __align__(8) __nv_bfloat16 h[4], l[4];
#pragma unroll
    for (int j = 0; j < 4; j++) {
        h[j] = __float2bfloat16(vv[j]);
        l[j] = __float2bfloat16(vv[j] - __bfloat162float(h[j]));
    }
    ((uint2*)hi)[i] = *(uint2*)h;
    ((uint2*)lo)[i] = *(uint2*)l;
}

// ===========================================================================
// split-bf16 GEMM on mma.sync:  C[M,N] = A[M,K] @ W[N,K]^T + bias[N]
// 128x128 CTA tile, BK=64 (128B rows, XOR-8 swizzle), 3-stage cp.async.
// ===========================================================================
#define MT_BYTES   16384
#define STAGE_B    (4 * MT_BYTES)
#define GEMM_SMEM  (3 * STAGE_B)         // 192 KB

__global__ __launch_bounds__(256, 1)
void gemm_mma_split(const __nv_bfloat16* __restrict__ Ahi,
                    const __nv_bfloat16* __restrict__ Alo,
                    const __nv_bfloat16* __restrict__ Whi,
                    const __nv_bfloat16* __restrict__ Wlo,
                    const float* __restrict__ bias,
                    float* __restrict__ C,
                    int N, int K)
{
    extern __shared__ __align__(1024) char smem[];
    const uint32_t sb = smem_u32(smem);

    const int tid  = threadIdx.x;
    const int lane = tid & 31;
    const int wid  = tid >> 5;
    const int warp_m = wid & 3;
    const int warp_n = wid >> 2;
    const int bm0 = blockIdx.y * 128;
    const int bn0 = blockIdx.x * 128;

    const int lr = tid >> 3;
    const int lc = tid & 7;

    const __nv_bfloat16* srcA[2] = { Ahi + (size_t)bm0 * K,  Alo + (size_t)bm0 * K };
    const __nv_bfloat16* srcW[2] = { Whi + (size_t)bn0 * K,  Wlo + (size_t)bn0 * K };

    const int NC = K / 64;

    auto issue_stage = [&](int kc, int stage) {
        const size_t koff = (size_t)kc * 64;
        const uint32_t stb = sb + stage * STAGE_B;
#pragma unroll
        for (int t = 0; t < 4; t++) {
            const __nv_bfloat16* base = (t < 2) ? srcA[t] : srcW[t - 2];
            const uint32_t tb = stb + t * MT_BYTES;
#pragma unroll
            for (int i = 0; i < 4; i++) {
                int rr = lr + i * 32;
                const __nv_bfloat16* src = base + (size_t)rr * K + koff + lc * 8;
                uint32_t dst = tb + rr * 128 + ((lc ^ (rr & 7)) * 16);
                CP_ASYNC16(dst, src);
            }
        }
    };

    float acc[2][8][4];
#pragma unroll
    for (int mt = 0; mt < 2; mt++)
#pragma unroll
        for (int nt = 0; nt < 8; nt++)
#pragma unroll
            for (int j = 0; j < 4; j++)
                acc[mt][nt][j] = 0.f;

    const int arow  = warp_m * 32 + (lane & 15);
    const int ahalf = lane >> 4;
    const int brow  = warp_n * 64 + ((lane >> 4) << 3) + (lane & 7);
    const int bhalf = (lane >> 3) & 1;

    issue_stage(0, 0); CP_COMMIT();
    issue_stage(1, 1); CP_COMMIT();

#pragma unroll 1
    for (int kc = 0; kc < NC; kc++) {
        if (kc + 2 < NC) issue_stage(kc + 2, (kc + 2) % 3);
        CP_COMMIT();
        CP_WAIT2();
        __syncthreads();

        const uint32_t stb = sb + (kc % 3) * STAGE_B;
        const uint32_t tAh = stb;
        const uint32_t tAl = stb + MT_BYTES;
        const uint32_t tWh = stb + 2 * MT_BYTES;
        const uint32_t tWl = stb + 3 * MT_BYTES;

#pragma unroll
        for (int ks = 0; ks < 4; ks++) {
            uint32_t ahi[2][4], alo[2][4], bhi[4][4], blo[4][4];
#pragma unroll
            for (int mt = 0; mt < 2; mt++) {
                int r  = arow + mt * 16;
                int ch = 2 * ks + ahalf;
                uint32_t off = r * 128 + ((ch ^ (r & 7)) * 16);
                LDSM_X4(ahi[mt], tAh + off);
                LDSM_X4(alo[mt], tAl + off);
            }
#pragma unroll
            for (int nt2 = 0; nt2 < 4; nt2++) {
                int r  = brow + nt2 * 16;
                int ch = 2 * ks + bhalf;
                uint32_t off = r * 128 + ((ch ^ (r & 7)) * 16);
                LDSM_X4(bhi[nt2], tWh + off);
                LDSM_X4(blo[nt2], tWl + off);
            }
#pragma unroll
            for (int mt = 0; mt < 2; mt++)
#pragma unroll
                for (int nt = 0; nt < 8; nt++) {
                    const uint32_t* bh = &bhi[nt >> 1][(nt & 1) * 2];
                    const uint32_t* bl = &blo[nt >> 1][(nt & 1) * 2];
                    MMA16816(acc[mt][nt], ahi[mt], bh[0], bh[1]);
                    MMA16816(acc[mt][nt], ahi[mt], bl[0], bl[1]);
                    MMA16816(acc[mt][nt], alo[mt], bh[0], bh[1]);
                }
        }
        __syncthreads();
    }

#pragma unroll
    for (int mt = 0; mt < 2; mt++) {
        int row0 = bm0 + warp_m * 32 + mt * 16 + (lane >> 2);
#pragma unroll
        for (int nt = 0; nt < 8; nt++) {
            int col = bn0 + warp_n * 64 + nt * 8 + (lane & 3) * 2;
            float b0 = bias[col], b1 = bias[col + 1];
            float2 o0 = { acc[mt][nt][0] + b0, acc[mt][nt][1] + b1 };
            float2 o1 = { acc[mt][nt][2] + b0, acc[mt][nt][3] + b1 };
            *(float2*)&C[(size_t)row0 * N + col]       = o0;
            *(float2*)&C[(size_t)(row0 + 8) * N + col] = o1;
        }
    }
}

// ===========================================================================
// Persistent layer-1 recurrence, 2-D partition.
// Grid 128 = 4 batch-quarters x 32 unit-groups (8 units each).
// Block: 256 threads; thread owns one (b, u) cell; u = tid&7, b = tid>>3.
// Weights [32 rows x 256] + h [32 x 256] stationary/staged in smem (stride 260).
// Quarter-local barrier (32 blocks). f32x2 packed FMA.
// Also emits y1 as bf16 (hi, lo) for the tensor-core layer-2 projection.
// ===========================================================================
#define REC1_SMEM ((32 * 260 + 32 * 260) * 4)   // 66560 B

__global__ __launch_bounds__(256, 1)
void lstm_rec1(const float* __restrict__ pre,   // [16][128][1024]
               const float* __restrict__ Whh,   // [1024][256]
               float* __restrict__ y1,          // [16][128][256]
               __nv_bfloat16* __restrict__ y1hi,
               __nv_bfloat16* __restrict__ y1lo)
{
    extern __shared__ __align__(1024) float sm1[];
    float* ws = sm1;                  // [32][260]
    float* hs = sm1 + 32 * 260;       // [32][260]
    const uint32_t hs_b = smem_u32(hs);

    const int tid = threadIdx.x;
    const int bq  = blockIdx.x >> 5;          // batch quarter 0..3
    const int ug  = blockIdx.x & 31;          // unit group 0..31
    const int u0  = ug * 8;
    const int b0  = bq * 32;

    const int u  = tid & 7;
    const int bl = tid >> 3;                  // 0..31

    // stationary weights: row lr = g*8+uu
    for (int i = tid; i < 32 * 256; i += 256) {
        int lr = i >> 8, k = i & 255;
        int g = lr >> 3, uu = lr & 7;
        ws[lr * 260 + k] = Whh[(size_t)(g * HH1 + u0 + uu) * HH1 + k];
    }
    unsigned lgen = 0;
    if (tid == 0) lgen = *(volatile unsigned*)&g_bgen[bq * 32];
    __syncthreads();

    const ulonglong2* h2 = (const ulonglong2*)(hs + bl * 260);
    const ulonglong2* w2[4];
#pragma unroll
    for (int g = 0; g < 4; g++)
        w2[g] = (const ulonglong2*)(ws + (g * 8 + u) * 260);

    float c = 0.f;

#pragma unroll 1
    for (int t = 0; t < T_STEPS; t++) {
        // hoist pre-gate loads (independent of matvec)
        const float* prow = pre + ((size_t)t * BATCH + b0 + bl) * (4 * HH1) + u0 + u;
        float p0 = prow[0], p1 = prow[HH1], p2 = prow[2 * HH1], p3 = prow[3 * HH1];

        float a0 = 0.f, a1 = 0.f, a2 = 0.f, a3 = 0.f;
        if (t > 0) {
            const float* hsrc = y1 + (size_t)(t - 1) * BATCH * HH1 + (size_t)b0 * HH1;
#pragma unroll
            for (int i = 0; i < 8; i++) {           // 2048 float4 total
                int flat = tid + i * 256;
                int row = flat >> 6;                // 64 float4 per 256-f row
                int c16 = flat & 63;
                CP_ASYNC16(hs_b + row * 1040 + c16 * 16,
                           hsrc + row * HH1 + c16 * 4);
            }
            CP_COMMIT(); CP_WAIT0();
            __syncthreads();

            unsigned long long acc2[4][2] = {{0,0},{0,0},{0,0},{0,0}};
#pragma unroll 8
            for (int k4 = 0; k4 < 64; k4++) {
                ulonglong2 hv = h2[k4];
#pragma unroll
                for (int g = 0; g < 4; g++) {
                    ulonglong2 wv = w2[g][k4];
                    FMA_F32X2(acc2[g][0], hv.x, wv.x);
                    FMA_F32X2(acc2[g][1], hv.y, wv.y);
                }
            }
            a0 = unpack_sum(acc2[0][0]) + unpack_sum(acc2[0][1]);
            a1 = unpack_sum(acc2[1][0]) + unpack_sum(acc2[1][1]);
            a2 = unpack_sum(acc2[2][0]) + unpack_sum(acc2[2][1]);
            a3 = unpack_sum(acc2[3][0]) + unpack_sum(acc2[3][1]);
        }

        float gi = p0 + a0, gf = p1 + a1, gg = p2 + a2, go = p3 + a3;
        float si = 1.f / (1.f + __expf(-gi));
        float sf = 1.f / (1.f + __expf(-gf));
        float so = 1.f / (1.f + __expf(-go));
        float tg = tanhf(gg);
        c = sf * c + si * tg;
        float h = so * tanhf(c);

        size_t oi = ((size_t)t * BATCH + b0 + bl) * HH1 + u0 + u;
        y1[oi] = h;
        __nv_bfloat16 hb = __float2bfloat16(h);
        y1hi[oi] = hb;
        y1lo[oi] = __float2bfloat16(h - __bfloat162float(hb));

        if (t < T_STEPS - 1)
            grid_sync_q(lgen, &g_bcnt[bq * 32], &g_bgen[bq * 32], 32);
    }
}

// ===========================================================================
// Persistent layer-2 recurrence, 2-D partition.
// Grid 128 = 4 batch-quarters x 32 unit-groups (16 units each).
// Block: 256 threads; thread owns 2 cells: u = tid&15, b = (tid>>4) and +16.
// Weights [64 x 512] + h [32 x 512] in smem (stride 516). f32x2 FMA.
// ===========================================================================
#define REC2_SMEM ((64 * 516 + 32 * 516) * 4)   // 198144 B

__global__ __launch_bounds__(256, 1)
void lstm_rec2(const float* __restrict__ pre,   // [16][128][2048]
               const float* __restrict__ Whh,   // [2048][512]
               float* __restrict__ out)         // [16][128][512]
{
    extern __shared__ __align__(1024) float sm2[];
    float* ws = sm2;                    // [64][516]
    float* hs = sm2 + 64 * 516;         // [32][516]
    const uint32_t hs_b = smem_u32(hs);

    const int tid = threadIdx.x;
    const int bq  = blockIdx.x >> 5;
    const int ug  = blockIdx.x & 31;
    const int u0  = ug * 16;
    const int b0  = bq * 32;

    const int u  = tid & 15;
    const int bh = tid >> 4;            // 0..15 -> batches bh, bh+16

    for (int i = tid; i < 64 * 512; i += 256) {
        int lr = i >> 9, k = i & 511;
        int g = lr >> 4, uu = lr & 15;
        ws[lr * 516 + k] = Whh[(size_t)(g * HH2 + u0 + uu) * HH2 + k];
    }
    unsigned lgen = 0;
    if (tid == 0) lgen = *(volatile unsigned*)&g_bgen[bq * 32];
    __syncthreads();

    const ulonglong2* h2a = (const ulonglong2*)(hs + bh * 516);
    const ulonglong2* h2b = (const ulonglong2*)(hs + (bh + 16) * 516);
    const ulonglong2* w2[4];
#pragma unroll
    for (int g = 0; g < 4; g++)
        w2[g] = (const ulonglong2*)(ws + (g * 16 + u) * 516);

    float c0 = 0.f, c1 = 0.f;

#pragma unroll 1
    for (int t = 0; t < T_STEPS; t++) {
        const float* prowA = pre + ((size_t)t * BATCH + b0 + bh) * (4 * HH2) + u0 + u;
        const float* prowB = prowA + (size_t)16 * 4 * HH2;
        float pA[4], pB[4];
#pragma unroll
        for (int g = 0; g < 4; g++) { pA[g] = prowA[g * HH2]; pB[g] = prowB[g * HH2]; }

        float aA[4] = {0.f, 0.f, 0.f, 0.f};
        float aB[4] = {0.f, 0.f, 0.f, 0.f};

        if (t > 0) {
            const float* hsrc = out + (size_t)(t - 1) * BATCH * HH2 + (size_t)b0 * HH2;
#pragma unroll
            for (int i = 0; i < 16; i++) {          // 4096 float4 total
                int flat = tid + i * 256;
                int row = flat >> 7;                // 128 float4 per 512-f row
                int c16 = flat & 127;
                CP_ASYNC16(hs_b + row * 2064 + c16 * 16,
                           hsrc + row * HH2 + c16 * 4);
            }
            CP_COMMIT(); CP_WAIT0();
            __syncthreads();

            unsigned long long accA[4][2] = {{0,0},{0,0},{0,0},{0,0}};
            unsigned long long accB[4][2] = {{0,0},{0,0},{0,0},{0,0}};
#pragma unroll 4
            for (int k4 = 0; k4 < 128; k4++) {
                ulonglong2 ha = h2a[k4];
                ulonglong2 hb = h2b[k4];
#pragma unroll
                for (int g = 0; g < 4; g++) {
                    ulonglong2 wv = w2[g][k4];
                    FMA_F32X2(accA[g][0], ha.x, wv.x);
                    FMA_F32X2(accA[g][1], ha.y, wv.y);
                    FMA_F32X2(accB[g][0], hb.x, wv.x);
                    FMA_F32X2(accB[g][1], hb.y, wv.y);
                }
            }
#pragma unroll
            for (int g = 0; g < 4; g++) {
                aA[g] = unpack_sum(accA[g][0]) + unpack_sum(accA[g][1]);
                aB[g] = unpack_sum(accB[g][0]) + unpack_sum(accB[g][1]);
            }
            __syncthreads();   // hs reuse next step
        }

        {
            float gi = pA[0] + aA[0], gf = pA[1] + aA[1];
            float gg = pA[2] + aA[2], go = pA[3] + aA[3];
            float si = 1.f / (1.f + __expf(-gi));
            float sf = 1.f / (1.f + __expf(-gf));
            float so = 1.f / (1.f + __expf(-go));
            float tg = tanhf(gg);
            c0 = sf * c0 + si * tg;
            out[((size_t)t * BATCH + b0 + bh) * HH2 + u0 + u] = so * tanhf(c0);
        }
        {
            float gi = pB[0] + aB[0], gf = pB[1] + aB[1];
            float gg = pB[2] + aB[2], go = pB[3] + aB[3];
            float si = 1.f / (1.f + __expf(-gi));
            float sf = 1.f / (1.f + __expf(-gf));
            float so = 1.f / (1.f + __expf(-go));
            float tg = tanhf(gg);
            c1 = sf * c1 + si * tg;
            out[((size_t)t * BATCH + b0 + bh + 16) * HH2 + u0 + u] = so * tanhf(c1);
        }

        if (t < T_STEPS - 1)
            grid_sync_q(lgen, &g_bcnt[bq * 32], &g_bgen[bq * 32], 32);
    }
}

// ---------------------------------------------------------------------------
extern "C" void kernel_launch(void* const* d_in, const int* in_sizes, int n_in,
                              void* d_out, int out_size)
{
    const float* inp  = (const float*)d_in[0];
    const float* Wih1 = (const float*)d_in[1];
    const float* Whh1 = (const float*)d_in[2];
    const float* b1   = (const float*)d_in[3];
    const float* Wih2 = (const float*)d_in[4];
    const float* Whh2 = (const float*)d_in[5];
    const float* b2   = (const float*)d_in[6];
    float* out = (float*)d_out;

    float *pre1, *y1, *pre2;
    cudaGetSymbolAddress((void**)&pre1, g_pre1);
    cudaGetSymbolAddress((void**)&y1,   g_y1);
    cudaGetSymbolAddress((void**)&pre2, g_pre2);

    __nv_bfloat16 *ahi, *alo, *whi, *wlo, *y1hi, *y1lo, *w2hi, *w2lo;
    cudaGetSymbolAddress((void**)&ahi,  g_Ahi);
    cudaGetSymbolAddress((void**)&alo,  g_Alo);
    cudaGetSymbolAddress((void**)&whi,  g_Whi);
    cudaGetSymbolAddress((void**)&wlo,  g_Wlo);
    cudaGetSymbolAddress((void**)&y1hi, g_Y1hi);
    cudaGetSymbolAddress((void**)&y1lo, g_Y1lo);
    cudaGetSymbolAddress((void**)&w2hi, g_W2hi);
    cudaGetSymbolAddress((void**)&w2lo, g_W2lo);

    cudaFuncSetAttribute(gemm_mma_split,
                         cudaFuncAttributeMaxDynamicSharedMemorySize, GEMM_SMEM);
    cudaFuncSetAttribute(lstm_rec1,
                         cudaFuncAttributeMaxDynamicSharedMemorySize, REC1_SMEM);
    cudaFuncSetAttribute(lstm_rec2,
                         cudaFuncAttributeMaxDynamicSharedMemorySize, REC2_SMEM);

    const int M = T_STEPS * BATCH;  // 2048

    // splits: inp, Wih1, Wih2
    {
        int n4a = M * IN_DIM / 4;
        split_bf16<<<(n4a + 255) / 256, 256>>>(inp, ahi, alo, n4a);
        int n4w = 4 * HH1 * IN_DIM / 4;
        split_bf16<<<(n4w + 255) / 256, 256>>>(Wih1, whi, wlo, n4w);
        int n4w2 = 4 * HH2 * HH1 / 4;
        split_bf16<<<(n4w2 + 255) / 256, 256>>>(Wih2, w2hi, w2lo, n4w2);
    }

    // Layer 1 input projection (tensor cores): pre1 = X @ Wih1^T + b1
    gemm_mma_split<<<dim3(4 * HH1 / 128, M / 128), 256, GEMM_SMEM>>>(
        ahi, alo, whi, wlo, b1, pre1, 4 * HH1, IN_DIM);

    // Layer 1 recurrence (persistent, also emits y1 bf16 hi/lo)
    lstm_rec1<<<128, 256, REC1_SMEM>>>(pre1, Whh1, y1, y1hi, y1lo);

    // Layer 2 input projection (tensor cores, K=256): pre2 = Y1 @ Wih2^T + b2
    gemm_mma_split<<<dim3(4 * HH2 / 128, M / 128), 256, GEMM_SMEM>>>(
        y1hi, y1lo, w2hi, w2lo, b2, pre2, 4 * HH2, HH1);

    // Layer 2 recurrence (persistent, h written straight into d_out)
    lstm_rec2<<<128, 256, REC2_SMEM>>>(pre2, Whh2, out);
}

// round 10
// speedup vs baseline: 2.4047x; 1.0276x over previous
#include <cuda_runtime.h>
#include <cuda_bf16.h>
#include <cstdint>
#include <math.h>

#define T_STEPS 16
#define BATCH   128
#define IN_DIM  12288
#define HH1     256
#define HH2     512

// ---------------- scratch (static __device__ globals; no runtime alloc) ----
__device__ float g_pre1[T_STEPS * BATCH * 4 * HH1];   //  8.4 MB
__device__ float g_y1  [T_STEPS * BATCH * HH1];       //  2.1 MB
__device__ float g_pre2[T_STEPS * BATCH * 4 * HH2];   // 16.8 MB

// split-bf16 staging
__device__ __nv_bfloat16 g_Ahi[T_STEPS * BATCH * IN_DIM];   // 50 MB
__device__ __nv_bfloat16 g_Alo[T_STEPS * BATCH * IN_DIM];   // 50 MB
__device__ __nv_bfloat16 g_Whi[4 * HH1 * IN_DIM];           // 25 MB
__device__ __nv_bfloat16 g_Wlo[4 * HH1 * IN_DIM];           // 25 MB
__device__ __nv_bfloat16 g_Y1hi[T_STEPS * BATCH * HH1];     //  1 MB
__device__ __nv_bfloat16 g_Y1lo[T_STEPS * BATCH * HH1];     //  1 MB
__device__ __nv_bfloat16 g_W2hi[4 * HH2 * HH1];             //  1 MB
__device__ __nv_bfloat16 g_W2lo[4 * HH2 * HH1];             //  1 MB

// quarter-local barrier state (stride 32 u32 = 128 B to avoid false sharing)
__device__ unsigned g_bcnt[4 * 32];
__device__ unsigned g_bgen[4 * 32];

// ===========================================================================
// helpers
// ===========================================================================
__device__ __forceinline__ uint32_t smem_u32(const void* p) {
    uint32_t a;
    asm("{ .reg .u64 t; cvta.to.shared.u64 t, %1; cvt.u32.u64 %0, t; }"
        : "=r"(a) : "l"(p));
    return a;
}

#define LDSM_X4(r, addr) \
    asm volatile("ldmatrix.sync.aligned.m8n8.x4.shared.b16 {%0,%1,%2,%3}, [%4];" \
        : "=r"((r)[0]), "=r"((r)[1]), "=r"((r)[2]), "=r"((r)[3]) : "r"(addr))

#define MMA16816(d, a, b0v, b1v) \
    asm volatile("mma.sync.aligned.m16n8k16.row.col.f32.bf16.bf16.f32 " \
        "{%0,%1,%2,%3}, {%4,%5,%6,%7}, {%8,%9}, {%0,%1,%2,%3};" \
        : "+f"((d)[0]), "+f"((d)[1]), "+f"((d)[2]), "+f"((d)[3]) \
        : "r"((a)[0]), "r"((a)[1]), "r"((a)[2]), "r"((a)[3]), \
          "r"(b0v), "r"(b1v))

#define CP_ASYNC16(dst, src) \
    asm volatile("cp.async.cg.shared.global [%0], [%1], 16;" \
        :: "r"(dst), "l"(src))
#define CP_COMMIT() asm volatile("cp.async.commit_group;" ::: "memory")
#define CP_WAIT0()  asm volatile("cp.async.wait_group 0;"  ::: "memory")
#define CP_WAIT1()  asm volatile("cp.async.wait_group 1;"  ::: "memory")

// packed dual-FMA: d.lo += a.lo*b.lo ; d.hi += a.hi*b.hi  (Blackwell f32x2)
#define FMA_F32X2(d, a, b) \
    asm("fma.rn.f32x2 %0, %1, %2, %0;" : "+l"(d) : "l"(a), "l"(b))

__device__ __forceinline__ float unpack_sum(unsigned long long v) {
    return __uint_as_float((unsigned)(v & 0xffffffffull)) +
           __uint_as_float((unsigned)(v >> 32));
}

// quarter-local device barrier over nblocks co-resident blocks
__device__ __forceinline__ void grid_sync_q(unsigned& lgen, unsigned* cnt,
                                            unsigned* gen, int nblocks) {
    __syncthreads();
    if (threadIdx.x == 0) {
        __threadfence();
        unsigned a = atomicAdd(cnt, 1);
        if (a == (unsigned)(nblocks - 1)) {
            *cnt = 0;
            __threadfence();
            atomicAdd(gen, 1);
        } else {
            while (*(volatile unsigned*)gen <= lgen) { }
            __threadfence();
        }
        lgen++;
    }
    __syncthreads();
}

// ===========================================================================
// fp32 -> (hi, lo) bf16 split
// ===========================================================================
__global__ __launch_bounds__(256)
void split_bf16(const float* __restrict__ x, __nv_bfloat16* __restrict__ hi,
                __nv_bfloat16* __restrict__ lo, int n4) {
    int i = blockIdx.x * blockDim.x + threadIdx.x;
    if (i >= n4) return;
    float4 v = ((const float4*)x)[i];
    float vv[4] = {v.x, v.y, v.z, v.w};
    __align__(8) __nv_bfloat16 h[4], l[4];
#pragma unroll
    for (int j = 0; j < 4; j++) {
        h[j] = __float2bfloat16(vv[j]);
        l[j] = __float2bfloat16(vv[j] - __bfloat162float(h[j]));
    }
    ((uint2*)hi)[i] = *(uint2*)h;
    ((uint2*)lo)[i] = *(uint2*)l;
}

// ===========================================================================
// split-bf16 GEMM on mma.sync:  C[M,N] = A[M,K] @ W[N,K]^T + bias[N]
// 128x64 CTA tile, 128 threads, 2 CTAs/SM. BK=64 (128B rows, XOR-8 swizzle),
// 2-stage cp.async (48 KB/stage). 4 warps, warp tile 32x64; 3 bf16 passes.
// ===========================================================================
#define A_T_BYTES  16384                 // 128x64 bf16
#define W_T_BYTES  8192                  // 64x64 bf16
#define STAGE_B    (2 * A_T_BYTES + 2 * W_T_BYTES)   // 48 KB
#define GEMM_SMEM  (2 * STAGE_B)                     // 96 KB

__global__ __launch_bounds__(128, 2)
void gemm_mma_split(const __nv_bfloat16* __restrict__ Ahi,
                    const __nv_bfloat16* __restrict__ Alo,
                    const __nv_bfloat16* __restrict__ Whi,
                    const __nv_bfloat16* __restrict__ Wlo,
                    const float* __restrict__ bias,
                    float* __restrict__ C,
                    int N, int K)
{
    extern __shared__ __align__(1024) char smem[];
    const uint32_t sb = smem_u32(smem);

    const int tid  = threadIdx.x;
    const int lane = tid & 31;
    const int wid  = tid >> 5;           // 0..3 (m direction, 32 rows each)
    const int bm0 = blockIdx.y * 128;
    const int bn0 = blockIdx.x * 64;

    const __nv_bfloat16* srcA[2] = { Ahi + (size_t)bm0 * K,  Alo + (size_t)bm0 * K };
    const __nv_bfloat16* srcW[2] = { Whi + (size_t)bn0 * K,  Wlo + (size_t)bn0 * K };

    const int NC = K / 64;

    auto issue_stage = [&](int kc, int stage) {
        const size_t koff = (size_t)kc * 64;
        const uint32_t stb = sb + stage * STAGE_B;
        // A tiles: 128 rows -> 1024 16B chunks each
#pragma unroll
        for (int t = 0; t < 2; t++) {
            const uint32_t tb = stb + t * A_T_BYTES;
#pragma unroll
            for (int i = 0; i < 8; i++) {
                int idx = tid + i * 128;
                int rr = idx >> 3, c16 = idx & 7;
                const __nv_bfloat16* src = srcA[t] + (size_t)rr * K + koff + c16 * 8;
                CP_ASYNC16(tb + rr * 128 + ((c16 ^ (rr & 7)) * 16), src);
            }
        }
        // W tiles: 64 rows -> 512 chunks each
#pragma unroll
        for (int t = 0; t < 2; t++) {
            const uint32_t tb = stb + 2 * A_T_BYTES + t * W_T_BYTES;
#pragma unroll
            for (int i = 0; i < 4; i++) {
                int idx = tid + i * 128;
                int rr = idx >> 3, c16 = idx & 7;
                const __nv_bfloat16* src = srcW[t] + (size_t)rr * K + koff + c16 * 8;
                CP_ASYNC16(tb + rr * 128 + ((c16 ^ (rr & 7)) * 16), src);
            }
        }
    };

    float acc[2][8][4];
#pragma unroll
    for (int mt = 0; mt < 2; mt++)
#pragma unroll
        for (int nt = 0; nt < 8; nt++)
#pragma unroll
            for (int j = 0; j < 4; j++)
                acc[mt][nt][j] = 0.f;

    const int arow  = wid * 32 + (lane & 15);
    const int ahalf = lane >> 4;
    const int brow  = ((lane >> 4) << 3) + (lane & 7);
    const int bhalf = (lane >> 3) & 1;

    issue_stage(0, 0); CP_COMMIT();

#pragma unroll 1
    for (int kc = 0; kc < NC; kc++) {
        if (kc + 1 < NC) issue_stage(kc + 1, (kc + 1) & 1);
        CP_COMMIT();
        CP_WAIT1();
        __syncthreads();

        const uint32_t stb = sb + (kc & 1) * STAGE_B;
        const uint32_t tAh = stb;
        const uint32_t tAl = stb + A_T_BYTES;
        const uint32_t tWh = stb + 2 * A_T_BYTES;
        const uint32_t tWl = stb + 2 * A_T_BYTES + W_T_BYTES;

#pragma unroll
        for (int ks = 0; ks < 4; ks++) {
            uint32_t ahi[2][4], alo[2][4], bhi[4][4], blo[4][4];
#pragma unroll
            for (int mt = 0; mt < 2; mt++) {
                int r  = arow + mt * 16;
                int ch = 2 * ks + ahalf;
                uint32_t off = r * 128 + ((ch ^ (r & 7)) * 16);
                LDSM_X4(ahi[mt], tAh + off);
                LDSM_X4(alo[mt], tAl + off);
            }
#pragma unroll
            for (int nt2 = 0; nt2 < 4; nt2++) {
                int r  = brow + nt2 * 16;
                int ch = 2 * ks + bhalf;
                uint32_t off = r * 128 + ((ch ^ (r & 7)) * 16);
                LDSM_X4(bhi[nt2], tWh + off);
                LDSM_X4(blo[nt2], tWl + off);
            }
#pragma unroll
            for (int mt = 0; mt < 2; mt++)
#pragma unroll
                for (int nt = 0; nt < 8; nt++) {
                    const uint32_t* bh = &bhi[nt >> 1][(nt & 1) * 2];
                    const uint32_t* bl = &blo[nt >> 1][(nt & 1) * 2];
                    MMA16816(acc[mt][nt], ahi[mt], bh[0], bh[1]);
                    MMA16816(acc[mt][nt], ahi[mt], bl[0], bl[1]);
                    MMA16816(acc[mt][nt], alo[mt], bh[0], bh[1]);
                }
        }
        __syncthreads();
    }

#pragma unroll
    for (int mt = 0; mt < 2; mt++) {
        int row0 = bm0 + wid * 32 + mt * 16 + (lane >> 2);
#pragma unroll
        for (int nt = 0; nt < 8; nt++) {
            int col = bn0 + nt * 8 + (lane & 3) * 2;
            float b0 = bias[col], b1 = bias[col + 1];
            float2 o0 = { acc[mt][nt][0] + b0, acc[mt][nt][1] + b1 };
            float2 o1 = { acc[mt][nt][2] + b0, acc[mt][nt][3] + b1 };
            *(float2*)&C[(size_t)row0 * N + col]       = o0;
            *(float2*)&C[(size_t)(row0 + 8) * N + col] = o1;
        }
    }
}

// ===========================================================================
// Persistent layer-1 recurrence (unchanged from R8)
// ===========================================================================
#define REC1_SMEM ((32 * 260 + 32 * 260) * 4)   // 66560 B

__global__ __launch_bounds__(256, 1)
void lstm_rec1(const float* __restrict__ pre,   // [16][128][1024]
               const float* __restrict__ Whh,   // [1024][256]
               float* __restrict__ y1,          // [16][128][256]
               __nv_bfloat16* __restrict__ y1hi,
               __nv_bfloat16* __restrict__ y1lo)
{
    extern __shared__ __align__(1024) float sm1[];
    float* ws = sm1;                  // [32][260]
    float* hs = sm1 + 32 * 260;       // [32][260]
    const uint32_t hs_b = smem_u32(hs);

    const int tid = threadIdx.x;
    const int bq  = blockIdx.x >> 5;
    const int ug  = blockIdx.x & 31;
    const int u0  = ug * 8;
    const int b0  = bq * 32;

    const int u  = tid & 7;
    const int bl = tid >> 3;

    for (int i = tid; i < 32 * 256; i += 256) {
        int lr = i >> 8, k = i & 255;
        int g = lr >> 3, uu = lr & 7;
        ws[lr * 260 + k] = Whh[(size_t)(g * HH1 + u0 + uu) * HH1 + k];
    }
    unsigned lgen = 0;
    if (tid == 0) lgen = *(volatile unsigned*)&g_bgen[bq * 32];
    __syncthreads();

    const ulonglong2* h2 = (const ulonglong2*)(hs + bl * 260);
    const ulonglong2* w2[4];
#pragma unroll
    for (int g = 0; g < 4; g++)
        w2[g] = (const ulonglong2*)(ws + (g * 8 + u) * 260);

    float c = 0.f;

#pragma unroll 1
    for (int t = 0; t < T_STEPS; t++) {
        const float* prow = pre + ((size_t)t * BATCH + b0 + bl) * (4 * HH1) + u0 + u;
        float p0 = prow[0], p1 = prow[HH1], p2 = prow[2 * HH1], p3 = prow[3 * HH1];

        float a0 = 0.f, a1 = 0.f, a2 = 0.f, a3 = 0.f;
        if (t > 0) {
            const float* hsrc = y1 + (size_t)(t - 1) * BATCH * HH1 + (size_t)b0 * HH1;
#pragma unroll
            for (int i = 0; i < 8; i++) {
                int flat = tid + i * 256;
                int row = flat >> 6;
                int c16 = flat & 63;
                CP_ASYNC16(hs_b + row * 1040 + c16 * 16,
                           hsrc + row * HH1 + c16 * 4);
            }
            CP_COMMIT(); CP_WAIT0();
            __syncthreads();

            unsigned long long acc2[4][2] = {{0,0},{0,0},{0,0},{0,0}};
#pragma unroll 8
            for (int k4 = 0; k4 < 64; k4++) {
                ulonglong2 hv = h2[k4];
#pragma unroll
                for (int g = 0; g < 4; g++) {
                    ulonglong2 wv = w2[g][k4];
                    FMA_F32X2(acc2[g][0], hv.x, wv.x);
                    FMA_F32X2(acc2[g][1], hv.y, wv.y);
                }
            }
            a0 = unpack_sum(acc2[0][0]) + unpack_sum(acc2[0][1]);
            a1 = unpack_sum(acc2[1][0]) + unpack_sum(acc2[1][1]);
            a2 = unpack_sum(acc2[2][0]) + unpack_sum(acc2[2][1]);
            a3 = unpack_sum(acc2[3][0]) + unpack_sum(acc2[3][1]);
        }

        float gi = p0 + a0, gf = p1 + a1, gg = p2 + a2, go = p3 + a3;
        float si = 1.f / (1.f + __expf(-gi));
        float sf = 1.f / (1.f + __expf(-gf));
        float so = 1.f / (1.f + __expf(-go));
        float tg = tanhf(gg);
        c = sf * c + si * tg;
        float h = so * tanhf(c);

        size_t oi = ((size_t)t * BATCH + b0 + bl) * HH1 + u0 + u;
        y1[oi] = h;
        __nv_bfloat16 hb = __float2bfloat16(h);
        y1hi[oi] = hb;
        y1lo[oi] = __float2bfloat16(h - __bfloat162float(hb));

        if (t < T_STEPS - 1)
            grid_sync_q(lgen, &g_bcnt[bq * 32], &g_bgen[bq * 32], 32);
    }
}

// ===========================================================================
// Persistent layer-2 recurrence (unchanged from R8)
// ===========================================================================
#define REC2_SMEM ((64 * 516 + 32 * 516) * 4)   // 198144 B

__global__ __launch_bounds__(256, 1)
void lstm_rec2(const float* __restrict__ pre,   // [16][128][2048]
               const float* __restrict__ Whh,   // [2048][512]
               float* __restrict__ out)         // [16][128][512]
{
    extern __shared__ __align__(1024) float sm2[];
    float* ws = sm2;                    // [64][516]
    float* hs = sm2 + 64 * 516;         // [32][516]
    const uint32_t hs_b = smem_u32(hs);

    const int tid = threadIdx.x;
    const int bq  = blockIdx.x >> 5;
    const int ug  = blockIdx.x & 31;
    const int u0  = ug * 16;
    const int b0  = bq * 32;

    const int u  = tid & 15;
    const int bh = tid >> 4;

    for (int i = tid; i < 64 * 512; i += 256) {
        int lr = i >> 9, k = i & 511;
        int g = lr >> 4, uu = lr & 15;
        ws[lr * 516 + k] = Whh[(size_t)(g * HH2 + u0 + uu) * HH2 + k];
    }
    unsigned lgen = 0;
    if (tid == 0) lgen = *(volatile unsigned*)&g_bgen[bq * 32];
    __syncthreads();

    const ulonglong2* h2a = (const ulonglong2*)(hs + bh * 516);
    const ulonglong2* h2b = (const ulonglong2*)(hs + (bh + 16) * 516);
    const ulonglong2* w2[4];
#pragma unroll
    for (int g = 0; g < 4; g++)
        w2[g] = (const ulonglong2*)(ws + (g * 16 + u) * 516);

    float c0 = 0.f, c1 = 0.f;

#pragma unroll 1
    for (int t = 0; t < T_STEPS; t++) {
        const float* prowA = pre + ((size_t)t * BATCH + b0 + bh) * (4 * HH2) + u0 + u;
        const float* prowB = prowA + (size_t)16 * 4 * HH2;
        float pA[4], pB[4];
#pragma unroll
        for (int g = 0; g < 4; g++) { pA[g] = prowA[g * HH2]; pB[g] = prowB[g * HH2]; }

        float aA[4] = {0.f, 0.f, 0.f, 0.f};
        float aB[4] = {0.f, 0.f, 0.f, 0.f};

        if (t > 0) {
            const float* hsrc = out + (size_t)(t - 1) * BATCH * HH2 + (size_t)b0 * HH2;
#pragma unroll
            for (int i = 0; i < 16; i++) {
                int flat = tid + i * 256;
                int row = flat >> 7;
                int c16 = flat & 127;
                CP_ASYNC16(hs_b + row * 2064 + c16 * 16,
                           hsrc + row * HH2 + c16 * 4);
            }
            CP_COMMIT(); CP_WAIT0();
            __syncthreads();

            unsigned long long accA[4][2] = {{0,0},{0,0},{0,0},{0,0}};
            unsigned long long accB[4][2] = {{0,0},{0,0},{0,0},{0,0}};
#pragma unroll 4
            for (int k4 = 0; k4 < 128; k4++) {
                ulonglong2 ha = h2a[k4];
                ulonglong2 hb = h2b[k4];
#pragma unroll
                for (int g = 0; g < 4; g++) {
                    ulonglong2 wv = w2[g][k4];
                    FMA_F32X2(accA[g][0], ha.x, wv.x);
                    FMA_F32X2(accA[g][1], ha.y, wv.y);
                    FMA_F32X2(accB[g][0], hb.x, wv.x);
                    FMA_F32X2(accB[g][1], hb.y, wv.y);
                }
            }
#pragma unroll
            for (int g = 0; g < 4; g++) {
                aA[g] = unpack_sum(accA[g][0]) + unpack_sum(accA[g][1]);
                aB[g] = unpack_sum(accB[g][0]) + unpack_sum(accB[g][1]);
            }
            __syncthreads();
        }

        {
            float gi = pA[0] + aA[0], gf = pA[1] + aA[1];
            float gg = pA[2] + aA[2], go = pA[3] + aA[3];
            float si = 1.f / (1.f + __expf(-gi));
            float sf = 1.f / (1.f + __expf(-gf));
            float so = 1.f / (1.f + __expf(-go));
            float tg = tanhf(gg);
            c0 = sf * c0 + si * tg;
            out[((size_t)t * BATCH + b0 + bh) * HH2 + u0 + u] = so * tanhf(c0);
        }
        {
            float gi = pB[0] + aB[0], gf = pB[1] + aB[1];
            float gg = pB[2] + aB[2], go = pB[3] + aB[3];
            float si = 1.f / (1.f + __expf(-gi));
            float sf = 1.f / (1.f + __expf(-gf));
            float so = 1.f / (1.f + __expf(-go));
            float tg = tanhf(gg);
            c1 = sf * c1 + si * tg;
            out[((size_t)t * BATCH + b0 + bh + 16) * HH2 + u0 + u] = so * tanhf(c1);
        }

        if (t < T_STEPS - 1)
            grid_sync_q(lgen, &g_bcnt[bq * 32], &g_bgen[bq * 32], 32);
    }
}

// ---------------------------------------------------------------------------
extern "C" void kernel_launch(void* const* d_in, const int* in_sizes, int n_in,
                              void* d_out, int out_size)
{
    const float* inp  = (const float*)d_in[0];
    const float* Wih1 = (const float*)d_in[1];
    const float* Whh1 = (const float*)d_in[2];
    const float* b1   = (const float*)d_in[3];
    const float* Wih2 = (const float*)d_in[4];
    const float* Whh2 = (const float*)d_in[5];
    const float* b2   = (const float*)d_in[6];
    float* out = (float*)d_out;

    float *pre1, *y1, *pre2;
    cudaGetSymbolAddress((void**)&pre1, g_pre1);
    cudaGetSymbolAddress((void**)&y1,   g_y1);
    cudaGetSymbolAddress((void**)&pre2, g_pre2);

    __nv_bfloat16 *ahi, *alo, *whi, *wlo, *y1hi, *y1lo, *w2hi, *w2lo;
    cudaGetSymbolAddress((void**)&ahi,  g_Ahi);
    cudaGetSymbolAddress((void**)&alo,  g_Alo);
    cudaGetSymbolAddress((void**)&whi,  g_Whi);
    cudaGetSymbolAddress((void**)&wlo,  g_Wlo);
    cudaGetSymbolAddress((void**)&y1hi, g_Y1hi);
    cudaGetSymbolAddress((void**)&y1lo, g_Y1lo);
    cudaGetSymbolAddress((void**)&w2hi, g_W2hi);
    cudaGetSymbolAddress((void**)&w2lo, g_W2lo);

    cudaFuncSetAttribute(gemm_mma_split,
                         cudaFuncAttributeMaxDynamicSharedMemorySize, GEMM_SMEM);
    cudaFuncSetAttribute(lstm_rec1,
                         cudaFuncAttributeMaxDynamicSharedMemorySize, REC1_SMEM);
    cudaFuncSetAttribute(lstm_rec2,
                         cudaFuncAttributeMaxDynamicSharedMemorySize, REC2_SMEM);

    const int M = T_STEPS * BATCH;  // 2048

    // splits: inp, Wih1, Wih2
    {
        int n4a = M * IN_DIM / 4;
        split_bf16<<<(n4a + 255) / 256, 256>>>(inp, ahi, alo, n4a);
        int n4w = 4 * HH1 * IN_DIM / 4;
        split_bf16<<<(n4w + 255) / 256, 256>>>(Wih1, whi, wlo, n4w);
        int n4w2 = 4 * HH2 * HH1 / 4;
        split_bf16<<<(n4w2 + 255) / 256, 256>>>(Wih2, w2hi, w2lo, n4w2);
    }

    // Layer 1 input projection (tensor cores): pre1 = X @ Wih1^T + b1
    gemm_mma_split<<<dim3(4 * HH1 / 64, M / 128), 128, GEMM_SMEM>>>(
        ahi, alo, whi, wlo, b1, pre1, 4 * HH1, IN_DIM);

    // Layer 1 recurrence (persistent, also emits y1 bf16 hi/lo)
    lstm_rec1<<<128, 256, REC1_SMEM>>>(pre1, Whh1, y1, y1hi, y1lo);

    // Layer 2 input projection (tensor cores, K=256): pre2 = Y1 @ Wih2^T + b2
    gemm_mma_split<<<dim3(4 * HH2 / 64, M / 128), 128, GEMM_SMEM>>>(
        y1hi, y1lo, w2hi, w2lo, b2, pre2, 4 * HH2, HH1);

    // Layer 2 recurrence (persistent, h written straight into d_out)
    lstm_rec2<<<128, 256, REC2_SMEM>>>(pre2, Whh2, out);
}

// round 11
// speedup vs baseline: 2.8547x; 1.1871x over previous
#include <cuda_runtime.h>
#include <cuda_fp16.h>
#include <cstdint>
#include <math.h>

#define T_STEPS 16
#define BATCH   128
#define IN_DIM  12288
#define HH1     256
#define HH2     512

// ---------------- scratch (static __device__ globals; no runtime alloc) ----
__device__ float g_pre1[T_STEPS * BATCH * 4 * HH1];   //  8.4 MB
__device__ float g_y1  [T_STEPS * BATCH * HH1];       //  2.1 MB
__device__ float g_pre2[T_STEPS * BATCH * 4 * HH2];   // 16.8 MB

// fp16 staging: A split (hi,lo), W rounded once
__device__ __half g_Ahi[T_STEPS * BATCH * IN_DIM];    // 50 MB
__device__ __half g_Alo[T_STEPS * BATCH * IN_DIM];    // 50 MB
__device__ __half g_Wf [4 * HH1 * IN_DIM];            // 25 MB
__device__ __half g_Y1hi[T_STEPS * BATCH * HH1];      //  1 MB
__device__ __half g_Y1lo[T_STEPS * BATCH * HH1];      //  1 MB
__device__ __half g_W2f[4 * HH2 * HH1];               //  1 MB

// quarter-local barrier state (stride 32 u32 = 128 B to avoid false sharing)
__device__ unsigned g_bcnt[4 * 32];
__device__ unsigned g_bgen[4 * 32];

// ===========================================================================
// helpers
// ===========================================================================
__device__ __forceinline__ uint32_t smem_u32(const void* p) {
    uint32_t a;
    asm("{ .reg .u64 t; cvta.to.shared.u64 t, %1; cvt.u32.u64 %0, t; }"
        : "=r"(a) : "l"(p));
    return a;
}

#define LDSM_X4(r, addr) \
    asm volatile("ldmatrix.sync.aligned.m8n8.x4.shared.b16 {%0,%1,%2,%3}, [%4];" \
        : "=r"((r)[0]), "=r"((r)[1]), "=r"((r)[2]), "=r"((r)[3]) : "r"(addr))

#define MMA16816H(d, a, b0v, b1v) \
    asm volatile("mma.sync.aligned.m16n8k16.row.col.f32.f16.f16.f32 " \
        "{%0,%1,%2,%3}, {%4,%5,%6,%7}, {%8,%9}, {%0,%1,%2,%3};" \
        : "+f"((d)[0]), "+f"((d)[1]), "+f"((d)[2]), "+f"((d)[3]) \
        : "r"((a)[0]), "r"((a)[1]), "r"((a)[2]), "r"((a)[3]), \
          "r"(b0v), "r"(b1v))

#define CP_ASYNC16(dst, src) \
    asm volatile("cp.async.cg.shared.global [%0], [%1], 16;" \
        :: "r"(dst), "l"(src))
#define CP_COMMIT() asm volatile("cp.async.commit_group;" ::: "memory")
#define CP_WAIT0()  asm volatile("cp.async.wait_group 0;"  ::: "memory")
#define CP_WAIT1()  asm volatile("cp.async.wait_group 1;"  ::: "memory")

// packed dual-FMA: d.lo += a.lo*b.lo ; d.hi += a.hi*b.hi  (Blackwell f32x2)
#define FMA_F32X2(d, a, b) \
    asm("fma.rn.f32x2 %0, %1, %2, %0;" : "+l"(d) : "l"(a), "l"(b))

__device__ __forceinline__ float unpack_sum(unsigned long long v) {
    return __uint_as_float((unsigned)(v & 0xffffffffull)) +
           __uint_as_float((unsigned)(v >> 32));
}

// quarter-local device barrier over nblocks co-resident blocks
__device__ __forceinline__ void grid_sync_q(unsigned& lgen, unsigned* cnt,
                                            unsigned* gen, int nblocks) {
    __syncthreads();
    if (threadIdx.x == 0) {
        __threadfence();
        unsigned a = atomicAdd(cnt, 1);
        if (a == (unsigned)(nblocks - 1)) {
            *cnt = 0;
            __threadfence();
            atomicAdd(gen, 1);
        } else {
            while (*(volatile unsigned*)gen <= lgen) { }
            __threadfence();
        }
        lgen++;
    }
    __syncthreads();
}

// ===========================================================================
// fp32 -> (hi, lo) fp16 split / fp32 -> fp16 round
// ===========================================================================
__global__ __launch_bounds__(256)
void split_f16(const float* __restrict__ x, __half* __restrict__ hi,
               __half* __restrict__ lo, int n4) {
    int i = blockIdx.x * blockDim.x + threadIdx.x;
    if (i >= n4) return;
    float4 v = ((const float4*)x)[i];
    float vv[4] = {v.x, v.y, v.z, v.w};
    __align__(8) __half h[4], l[4];
#pragma unroll
    for (int j = 0; j < 4; j++) {
        h[j] = __float2half_rn(vv[j]);
        l[j] = __float2half_rn(vv[j] - __half2float(h[j]));
    }
    ((uint2*)hi)[i] = *(uint2*)h;
    ((uint2*)lo)[i] = *(uint2*)l;
}

__global__ __launch_bounds__(256)
void conv_f16(const float* __restrict__ x, __half* __restrict__ w, int n4) {
    int i = blockIdx.x * blockDim.x + threadIdx.x;
    if (i >= n4) return;
    float4 v = ((const float4*)x)[i];
    __align__(8) __half h[4] = { __float2half_rn(v.x), __float2half_rn(v.y),
                                 __float2half_rn(v.z), __float2half_rn(v.w) };
    ((uint2*)w)[i] = *(uint2*)h;
}

// ===========================================================================
// fp16 2-pass GEMM on mma.sync:  C[M,N] = (Ahi+Alo)[M,K] @ Wf[N,K]^T + bias[N]
// 128x64 CTA tile, 128 threads, 2 CTAs/SM. BK=64 (128B rows, XOR-8 swizzle),
// 2-stage cp.async (40 KB/stage). 4 warps, warp tile 32x64; 2 fp16 passes.
// ===========================================================================
#define A_T_BYTES  16384                 // 128x64 fp16
#define W_T_BYTES  8192                  // 64x64 fp16
#define STAGE_B    (2 * A_T_BYTES + W_T_BYTES)       // 40 KB
#define GEMM_SMEM  (2 * STAGE_B)                     // 80 KB

__global__ __launch_bounds__(128, 2)
void gemm_mma_f16(const __half* __restrict__ Ahi,
                  const __half* __restrict__ Alo,
                  const __half* __restrict__ Wf,
                  const float* __restrict__ bias,
                  float* __restrict__ C,
                  int N, int K)
{
    extern __shared__ __align__(1024) char smem[];
    const uint32_t sb = smem_u32(smem);

    const int tid  = threadIdx.x;
    const int lane = tid & 31;
    const int wid  = tid >> 5;           // 0..3 (m direction, 32 rows each)
    const int bm0 = blockIdx.y * 128;
    const int bn0 = blockIdx.x * 64;

    const __half* srcA[2] = { Ahi + (size_t)bm0 * K,  Alo + (size_t)bm0 * K };
    const __half* srcW    =   Wf  + (size_t)bn0 * K;

    const int NC = K / 64;

    auto issue_stage = [&](int kc, int stage) {
        const size_t koff = (size_t)kc * 64;
        const uint32_t stb = sb + stage * STAGE_B;
        // A tiles: 128 rows -> 1024 16B chunks each
#pragma unroll
        for (int t = 0; t < 2; t++) {
            const uint32_t tb = stb + t * A_T_BYTES;
#pragma unroll
            for (int i = 0; i < 8; i++) {
                int idx = tid + i * 128;
                int rr = idx >> 3, c16 = idx & 7;
                const __half* src = srcA[t] + (size_t)rr * K + koff + c16 * 8;
                CP_ASYNC16(tb + rr * 128 + ((c16 ^ (rr & 7)) * 16), src);
            }
        }
        // W tile: 64 rows -> 512 chunks
        {
            const uint32_t tb = stb + 2 * A_T_BYTES;
#pragma unroll
            for (int i = 0; i < 4; i++) {
                int idx = tid + i * 128;
                int rr = idx >> 3, c16 = idx & 7;
                const __half* src = srcW + (size_t)rr * K + koff + c16 * 8;
                CP_ASYNC16(tb + rr * 128 + ((c16 ^ (rr & 7)) * 16), src);
            }
        }
    };

    float acc[2][8][4];
#pragma unroll
    for (int mt = 0; mt < 2; mt++)
#pragma unroll
        for (int nt = 0; nt < 8; nt++)
#pragma unroll
            for (int j = 0; j < 4; j++)
                acc[mt][nt][j] = 0.f;

    const int arow  = wid * 32 + (lane & 15);
    const int ahalf = lane >> 4;
    const int brow  = ((lane >> 4) << 3) + (lane & 7);
    const int bhalf = (lane >> 3) & 1;

    issue_stage(0, 0); CP_COMMIT();

#pragma unroll 1
    for (int kc = 0; kc < NC; kc++) {
        if (kc + 1 < NC) issue_stage(kc + 1, (kc + 1) & 1);
        CP_COMMIT();
        CP_WAIT1();
        __syncthreads();

        const uint32_t stb = sb + (kc & 1) * STAGE_B;
        const uint32_t tAh = stb;
        const uint32_t tAl = stb + A_T_BYTES;
        const uint32_t tW  = stb + 2 * A_T_BYTES;

#pragma unroll
        for (int ks = 0; ks < 4; ks++) {
            uint32_t ahi[2][4], alo[2][4], bf[4][4];
#pragma unroll
            for (int mt = 0; mt < 2; mt++) {
                int r  = arow + mt * 16;
                int ch = 2 * ks + ahalf;
                uint32_t off = r * 128 + ((ch ^ (r & 7)) * 16);
                LDSM_X4(ahi[mt], tAh + off);
                LDSM_X4(alo[mt], tAl + off);
            }
#pragma unroll
            for (int nt2 = 0; nt2 < 4; nt2++) {
                int r  = brow + nt2 * 16;
                int ch = 2 * ks + bhalf;
                uint32_t off = r * 128 + ((ch ^ (r & 7)) * 16);
                LDSM_X4(bf[nt2], tW + off);
            }
#pragma unroll
            for (int mt = 0; mt < 2; mt++)
#pragma unroll
                for (int nt = 0; nt < 8; nt++) {
                    const uint32_t* bv = &bf[nt >> 1][(nt & 1) * 2];
                    MMA16816H(acc[mt][nt], ahi[mt], bv[0], bv[1]);
                    MMA16816H(acc[mt][nt], alo[mt], bv[0], bv[1]);
                }
        }
        __syncthreads();
    }

#pragma unroll
    for (int mt = 0; mt < 2; mt++) {
        int row0 = bm0 + wid * 32 + mt * 16 + (lane >> 2);
#pragma unroll
        for (int nt = 0; nt < 8; nt++) {
            int col = bn0 + nt * 8 + (lane & 3) * 2;
            float b0 = bias[col], b1 = bias[col + 1];
            float2 o0 = { acc[mt][nt][0] + b0, acc[mt][nt][1] + b1 };
            float2 o1 = { acc[mt][nt][2] + b0, acc[mt][nt][3] + b1 };
            *(float2*)&C[(size_t)row0 * N + col]       = o0;
            *(float2*)&C[(size_t)(row0 + 8) * N + col] = o1;
        }
    }
}

// ===========================================================================
// Persistent layer-1 recurrence (2-D partition; emits y1 fp16 hi/lo)
// ===========================================================================
#define REC1_SMEM ((32 * 260 + 32 * 260) * 4)   // 66560 B

__global__ __launch_bounds__(256, 1)
void lstm_rec1(const float* __restrict__ pre,   // [16][128][1024]
               const float* __restrict__ Whh,   // [1024][256]
               float* __restrict__ y1,          // [16][128][256]
               __half* __restrict__ y1hi,
               __half* __restrict__ y1lo)
{
    extern __shared__ __align__(1024) float sm1[];
    float* ws = sm1;                  // [32][260]
    float* hs = sm1 + 32 * 260;       // [32][260]
    const uint32_t hs_b = smem_u32(hs);

    const int tid = threadIdx.x;
    const int bq  = blockIdx.x >> 5;
    const int ug  = blockIdx.x & 31;
    const int u0  = ug * 8;
    const int b0  = bq * 32;

    const int u  = tid & 7;
    const int bl = tid >> 3;

    for (int i = tid; i < 32 * 256; i += 256) {
        int lr = i >> 8, k = i & 255;
        int g = lr >> 3, uu = lr & 7;
        ws[lr * 260 + k] = Whh[(size_t)(g * HH1 + u0 + uu) * HH1 + k];
    }
    unsigned lgen = 0;
    if (tid == 0) lgen = *(volatile unsigned*)&g_bgen[bq * 32];
    __syncthreads();

    const ulonglong2* h2 = (const ulonglong2*)(hs + bl * 260);
    const ulonglong2* w2[4];
#pragma unroll
    for (int g = 0; g < 4; g++)
        w2[g] = (const ulonglong2*)(ws + (g * 8 + u) * 260);

    float c = 0.f;

#pragma unroll 1
    for (int t = 0; t < T_STEPS; t++) {
        const float* prow = pre + ((size_t)t * BATCH + b0 + bl) * (4 * HH1) + u0 + u;
        float p0 = prow[0], p1 = prow[HH1], p2 = prow[2 * HH1], p3 = prow[3 * HH1];

        float a0 = 0.f, a1 = 0.f, a2 = 0.f, a3 = 0.f;
        if (t > 0) {
            const float* hsrc = y1 + (size_t)(t - 1) * BATCH * HH1 + (size_t)b0 * HH1;
#pragma unroll
            for (int i = 0; i < 8; i++) {
                int flat = tid + i * 256;
                int row = flat >> 6;
                int c16 = flat & 63;
                CP_ASYNC16(hs_b + row * 1040 + c16 * 16,
                           hsrc + row * HH1 + c16 * 4);
            }
            CP_COMMIT(); CP_WAIT0();
            __syncthreads();

            unsigned long long acc2[4][2] = {{0,0},{0,0},{0,0},{0,0}};
#pragma unroll 8
            for (int k4 = 0; k4 < 64; k4++) {
                ulonglong2 hv = h2[k4];
#pragma unroll
                for (int g = 0; g < 4; g++) {
                    ulonglong2 wv = w2[g][k4];
                    FMA_F32X2(acc2[g][0], hv.x, wv.x);
                    FMA_F32X2(acc2[g][1], hv.y, wv.y);
                }
            }
            a0 = unpack_sum(acc2[0][0]) + unpack_sum(acc2[0][1]);
            a1 = unpack_sum(acc2[1][0]) + unpack_sum(acc2[1][1]);
            a2 = unpack_sum(acc2[2][0]) + unpack_sum(acc2[2][1]);
            a3 = unpack_sum(acc2[3][0]) + unpack_sum(acc2[3][1]);
        }

        float gi = p0 + a0, gf = p1 + a1, gg = p2 + a2, go = p3 + a3;
        float si = 1.f / (1.f + __expf(-gi));
        float sf = 1.f / (1.f + __expf(-gf));
        float so = 1.f / (1.f + __expf(-go));
        float tg = tanhf(gg);
        c = sf * c + si * tg;
        float h = so * tanhf(c);

        size_t oi = ((size_t)t * BATCH + b0 + bl) * HH1 + u0 + u;
        y1[oi] = h;
        __half hb = __float2half_rn(h);
        y1hi[oi] = hb;
        y1lo[oi] = __float2half_rn(h - __half2float(hb));

        if (t < T_STEPS - 1)
            grid_sync_q(lgen, &g_bcnt[bq * 32], &g_bgen[bq * 32], 32);
    }
}

// ===========================================================================
// Persistent layer-2 recurrence (unchanged)
// ===========================================================================
#define REC2_SMEM ((64 * 516 + 32 * 516) * 4)   // 198144 B

__global__ __launch_bounds__(256, 1)
void lstm_rec2(const float* __restrict__ pre,   // [16][128][2048]
               const float* __restrict__ Whh,   // [2048][512]
               float* __restrict__ out)         // [16][128][512]
{
    extern __shared__ __align__(1024) float sm2[];
    float* ws = sm2;                    // [64][516]
    float* hs = sm2 + 64 * 516;         // [32][516]
    const uint32_t hs_b = smem_u32(hs);

    const int tid = threadIdx.x;
    const int bq  = blockIdx.x >> 5;
    const int ug  = blockIdx.x & 31;
    const int u0  = ug * 16;
    const int b0  = bq * 32;

    const int u  = tid & 15;
    const int bh = tid >> 4;

    for (int i = tid; i < 64 * 512; i += 256) {
        int lr = i >> 9, k = i & 511;
        int g = lr >> 4, uu = lr & 15;
        ws[lr * 516 + k] = Whh[(size_t)(g * HH2 + u0 + uu) * HH2 + k];
    }
    unsigned lgen = 0;
    if (tid == 0) lgen = *(volatile unsigned*)&g_bgen[bq * 32];
    __syncthreads();

    const ulonglong2* h2a = (const ulonglong2*)(hs + bh * 516);
    const ulonglong2* h2b = (const ulonglong2*)(hs + (bh + 16) * 516);
    const ulonglong2* w2[4];
#pragma unroll
    for (int g = 0; g < 4; g++)
        w2[g] = (const ulonglong2*)(ws + (g * 16 + u) * 516);

    float c0 = 0.f, c1 = 0.f;

#pragma unroll 1
    for (int t = 0; t < T_STEPS; t++) {
        const float* prowA = pre + ((size_t)t * BATCH + b0 + bh) * (4 * HH2) + u0 + u;
        const float* prowB = prowA + (size_t)16 * 4 * HH2;
        float pA[4], pB[4];
#pragma unroll
        for (int g = 0; g < 4; g++) { pA[g] = prowA[g * HH2]; pB[g] = prowB[g * HH2]; }

        float aA[4] = {0.f, 0.f, 0.f, 0.f};
        float aB[4] = {0.f, 0.f, 0.f, 0.f};

        if (t > 0) {
            const float* hsrc = out + (size_t)(t - 1) * BATCH * HH2 + (size_t)b0 * HH2;
#pragma unroll
            for (int i = 0; i < 16; i++) {
                int flat = tid + i * 256;
                int row = flat >> 7;
                int c16 = flat & 127;
                CP_ASYNC16(hs_b + row * 2064 + c16 * 16,
                           hsrc + row * HH2 + c16 * 4);
            }
            CP_COMMIT(); CP_WAIT0();
            __syncthreads();

            unsigned long long accA[4][2] = {{0,0},{0,0},{0,0},{0,0}};
            unsigned long long accB[4][2] = {{0,0},{0,0},{0,0},{0,0}};
#pragma unroll 4
            for (int k4 = 0; k4 < 128; k4++) {
                ulonglong2 ha = h2a[k4];
                ulonglong2 hb = h2b[k4];
#pragma unroll
                for (int g = 0; g < 4; g++) {
                    ulonglong2 wv = w2[g][k4];
                    FMA_F32X2(accA[g][0], ha.x, wv.x);
                    FMA_F32X2(accA[g][1], ha.y, wv.y);
                    FMA_F32X2(accB[g][0], hb.x, wv.x);
                    FMA_F32X2(accB[g][1], hb.y, wv.y);
                }
            }
#pragma unroll
            for (int g = 0; g < 4; g++) {
                aA[g] = unpack_sum(accA[g][0]) + unpack_sum(accA[g][1]);
                aB[g] = unpack_sum(accB[g][0]) + unpack_sum(accB[g][1]);
            }
            __syncthreads();
        }

        {
            float gi = pA[0] + aA[0], gf = pA[1] + aA[1];
            float gg = pA[2] + aA[2], go = pA[3] + aA[3];
            float si = 1.f / (1.f + __expf(-gi));
            float sf = 1.f / (1.f + __expf(-gf));
            float so = 1.f / (1.f + __expf(-go));
            float tg = tanhf(gg);
            c0 = sf * c0 + si * tg;
            out[((size_t)t * BATCH + b0 + bh) * HH2 + u0 + u] = so * tanhf(c0);
        }
        {
            float gi = pB[0] + aB[0], gf = pB[1] + aB[1];
            float gg = pB[2] + aB[2], go = pB[3] + aB[3];
            float si = 1.f / (1.f + __expf(-gi));
            float sf = 1.f / (1.f + __expf(-gf));
            float so = 1.f / (1.f + __expf(-go));
            float tg = tanhf(gg);
            c1 = sf * c1 + si * tg;
            out[((size_t)t * BATCH + b0 + bh + 16) * HH2 + u0 + u] = so * tanhf(c1);
        }

        if (t < T_STEPS - 1)
            grid_sync_q(lgen, &g_bcnt[bq * 32], &g_bgen[bq * 32], 32);
    }
}

// ---------------------------------------------------------------------------
extern "C" void kernel_launch(void* const* d_in, const int* in_sizes, int n_in,
                              void* d_out, int out_size)
{
    const float* inp  = (const float*)d_in[0];
    const float* Wih1 = (const float*)d_in[1];
    const float* Whh1 = (const float*)d_in[2];
    const float* b1   = (const float*)d_in[3];
    const float* Wih2 = (const float*)d_in[4];
    const float* Whh2 = (const float*)d_in[5];
    const float* b2   = (const float*)d_in[6];
    float* out = (float*)d_out;

    float *pre1, *y1, *pre2;
    cudaGetSymbolAddress((void**)&pre1, g_pre1);
    cudaGetSymbolAddress((void**)&y1,   g_y1);
    cudaGetSymbolAddress((void**)&pre2, g_pre2);

    __half *ahi, *alo, *wf, *y1hi, *y1lo, *w2f;
    cudaGetSymbolAddress((void**)&ahi,  g_Ahi);
    cudaGetSymbolAddress((void**)&alo,  g_Alo);
    cudaGetSymbolAddress((void**)&wf,   g_Wf);
    cudaGetSymbolAddress((void**)&y1hi, g_Y1hi);
    cudaGetSymbolAddress((void**)&y1lo, g_Y1lo);
    cudaGetSymbolAddress((void**)&w2f,  g_W2f);

    cudaFuncSetAttribute(gemm_mma_f16,
                         cudaFuncAttributeMaxDynamicSharedMemorySize, GEMM_SMEM);
    cudaFuncSetAttribute(lstm_rec1,
                         cudaFuncAttributeMaxDynamicSharedMemorySize, REC1_SMEM);
    cudaFuncSetAttribute(lstm_rec2,
                         cudaFuncAttributeMaxDynamicSharedMemorySize, REC2_SMEM);

    const int M = T_STEPS * BATCH;  // 2048

    // splits: inp -> fp16 (hi,lo); Wih1, Wih2 -> fp16
    {
        int n4a = M * IN_DIM / 4;
        split_f16<<<(n4a + 255) / 256, 256>>>(inp, ahi, alo, n4a);
        int n4w = 4 * HH1 * IN_DIM / 4;
        conv_f16<<<(n4w + 255) / 256, 256>>>(Wih1, wf, n4w);
        int n4w2 = 4 * HH2 * HH1 / 4;
        conv_f16<<<(n4w2 + 255) / 256, 256>>>(Wih2, w2f, n4w2);
    }

    // Layer 1 input projection (tensor cores, fp16 2-pass): pre1 = X @ Wih1^T + b1
    gemm_mma_f16<<<dim3(4 * HH1 / 64, M / 128), 128, GEMM_SMEM>>>(
        ahi, alo, wf, b1, pre1, 4 * HH1, IN_DIM);

    // Layer 1 recurrence (persistent, emits y1 fp16 hi/lo)
    lstm_rec1<<<128, 256, REC1_SMEM>>>(pre1, Whh1, y1, y1hi, y1lo);

    // Layer 2 input projection (tensor cores, K=256): pre2 = Y1 @ Wih2^T + b2
    gemm_mma_f16<<<dim3(4 * HH2 / 64, M / 128), 128, GEMM_SMEM>>>(
        y1hi, y1lo, w2f, b2, pre2, 4 * HH2, HH1);

    // Layer 2 recurrence (persistent, h written straight into d_out)
    lstm_rec2<<<128, 256, REC2_SMEM>>>(pre2, Whh2, out);
}

// round 12
// speedup vs baseline: 3.5506x; 1.2438x over previous
#include <cuda_runtime.h>
#include <cuda_fp16.h>
#include <cstdint>
#include <math.h>

#define T_STEPS 16
#define BATCH   128
#define IN_DIM  12288
#define HH1     256
#define HH2     512

// ---------------- scratch (static __device__ globals; no runtime alloc) ----
__device__ float g_pre1[T_STEPS * BATCH * 4 * HH1];   //  8.4 MB
__device__ float g_y1  [T_STEPS * BATCH * HH1];       //  2.1 MB
__device__ float g_pre2[T_STEPS * BATCH * 4 * HH2];   // 16.8 MB

// fp16 staging: A split (hi,lo), W rounded once
__device__ __half g_Ahi[T_STEPS * BATCH * IN_DIM];    // 50 MB
__device__ __half g_Alo[T_STEPS * BATCH * IN_DIM];    // 50 MB
__device__ __half g_Wf [4 * HH1 * IN_DIM];            // 25 MB
__device__ __half g_Y1hi[T_STEPS * BATCH * HH1];      //  1 MB
__device__ __half g_Y1lo[T_STEPS * BATCH * HH1];      //  1 MB
__device__ __half g_W2f[4 * HH2 * HH1];               //  1 MB

// per-quarter h staging for tensorized layer-2 recurrence
__device__ __half g_H2hi[4 * 32 * HH2];
__device__ __half g_H2lo[4 * 32 * HH2];

// quarter-local barrier state (stride 32 u32 = 128 B to avoid false sharing)
__device__ unsigned g_bcnt[4 * 32];
__device__ unsigned g_bgen[4 * 32];

// ===========================================================================
// helpers
// ===========================================================================
__device__ __forceinline__ uint32_t smem_u32(const void* p) {
    uint32_t a;
    asm("{ .reg .u64 t; cvta.to.shared.u64 t, %1; cvt.u32.u64 %0, t; }"
        : "=r"(a) : "l"(p));
    return a;
}

#define LDSM_X4(r, addr) \
    asm volatile("ldmatrix.sync.aligned.m8n8.x4.shared.b16 {%0,%1,%2,%3}, [%4];" \
        : "=r"((r)[0]), "=r"((r)[1]), "=r"((r)[2]), "=r"((r)[3]) : "r"(addr))

#define MMA16816H(d, a, b0v, b1v) \
    asm volatile("mma.sync.aligned.m16n8k16.row.col.f32.f16.f16.f32 " \
        "{%0,%1,%2,%3}, {%4,%5,%6,%7}, {%8,%9}, {%0,%1,%2,%3};" \
        : "+f"((d)[0]), "+f"((d)[1]), "+f"((d)[2]), "+f"((d)[3]) \
        : "r"((a)[0]), "r"((a)[1]), "r"((a)[2]), "r"((a)[3]), \
          "r"(b0v), "r"(b1v))

#define CP_ASYNC16(dst, src) \
    asm volatile("cp.async.cg.shared.global [%0], [%1], 16;" \
        :: "r"(dst), "l"(src))
#define CP_COMMIT() asm volatile("cp.async.commit_group;" ::: "memory")
#define CP_WAIT0()  asm volatile("cp.async.wait_group 0;"  ::: "memory")
#define CP_WAIT1()  asm volatile("cp.async.wait_group 1;"  ::: "memory")

// packed dual-FMA: d.lo += a.lo*b.lo ; d.hi += a.hi*b.hi  (Blackwell f32x2)
#define FMA_F32X2(d, a, b) \
    asm("fma.rn.f32x2 %0, %1, %2, %0;" : "+l"(d) : "l"(a), "l"(b))

__device__ __forceinline__ float unpack_sum(unsigned long long v) {
    return __uint_as_float((unsigned)(v & 0xffffffffull)) +
           __uint_as_float((unsigned)(v >> 32));
}

// quarter-local device barrier over nblocks co-resident blocks
__device__ __forceinline__ void grid_sync_q(unsigned& lgen, unsigned* cnt,
                                            unsigned* gen, int nblocks) {
    __syncthreads();
    if (threadIdx.x == 0) {
        __threadfence();
        unsigned a = atomicAdd(cnt, 1);
        if (a == (unsigned)(nblocks - 1)) {
            *cnt = 0;
            __threadfence();
            atomicAdd(gen, 1);
        } else {
            while (*(volatile unsigned*)gen <= lgen) { }
            __threadfence();
        }
        lgen++;
    }
    __syncthreads();
}

// ===========================================================================
// fp32 -> (hi, lo) fp16 split / fp32 -> fp16 round
// ===========================================================================
__global__ __launch_bounds__(256)
void split_f16(const float* __restrict__ x, __half* __restrict__ hi,
               __half* __restrict__ lo, int n4) {
    int i = blockIdx.x * blockDim.x + threadIdx.x;
    if (i >= n4) return;
    float4 v = ((const float4*)x)[i];
    float vv[4] = {v.x, v.y, v.z, v.w};
    __align__(8) __half h[4], l[4];
#pragma unroll
    for (int j = 0; j < 4; j++) {
        h[j] = __float2half_rn(vv[j]);
        l[j] = __float2half_rn(vv[j] - __half2float(h[j]));
    }
    ((uint2*)hi)[i] = *(uint2*)h;
    ((uint2*)lo)[i] = *(uint2*)l;
}

__global__ __launch_bounds__(256)
void conv_f16(const float* __restrict__ x, __half* __restrict__ w, int n4) {
    int i = blockIdx.x * blockDim.x + threadIdx.x;
    if (i >= n4) return;
    float4 v = ((const float4*)x)[i];
    __align__(8) __half h[4] = { __float2half_rn(v.x), __float2half_rn(v.y),
                                 __float2half_rn(v.z), __float2half_rn(v.w) };
    ((uint2*)w)[i] = *(uint2*)h;
}

// ===========================================================================
// fp16 2-pass GEMM on mma.sync:  C[M,N] = (Ahi+Alo)[M,K] @ Wf[N,K]^T + bias[N]
// (unchanged from R11)
// ===========================================================================
#define A_T_BYTES  16384                 // 128x64 fp16
#define W_T_BYTES  8192                  // 64x64 fp16
#define STAGE_B    (2 * A_T_BYTES + W_T_BYTES)       // 40 KB
#define GEMM_SMEM  (2 * STAGE_B)                     // 80 KB

__global__ __launch_bounds__(128, 2)
void gemm_mma_f16(const __half* __restrict__ Ahi,
                  const __half* __restrict__ Alo,
                  const __half* __restrict__ Wf,
                  const float* __restrict__ bias,
                  float* __restrict__ C,
                  int N, int K)
{
    extern __shared__ __align__(1024) char smem[];
    const uint32_t sb = smem_u32(smem);

    const int tid  = threadIdx.x;
    const int lane = tid & 31;
    const int wid  = tid >> 5;
    const int bm0 = blockIdx.y * 128;
    const int bn0 = blockIdx.x * 64;

    const __half* srcA[2] = { Ahi + (size_t)bm0 * K,  Alo + (size_t)bm0 * K };
    const __half* srcW    =   Wf  + (size_t)bn0 * K;

    const int NC = K / 64;

    auto issue_stage = [&](int kc, int stage) {
        const size_t koff = (size_t)kc * 64;
        const uint32_t stb = sb + stage * STAGE_B;
#pragma unroll
        for (int t = 0; t < 2; t++) {
            const uint32_t tb = stb + t * A_T_BYTES;
#pragma unroll
            for (int i = 0; i < 8; i++) {
                int idx = tid + i * 128;
                int rr = idx >> 3, c16 = idx & 7;
                const __half* src = srcA[t] + (size_t)rr * K + koff + c16 * 8;
                CP_ASYNC16(tb + rr * 128 + ((c16 ^ (rr & 7)) * 16), src);
            }
        }
        {
            const uint32_t tb = stb + 2 * A_T_BYTES;
#pragma unroll
            for (int i = 0; i < 4; i++) {
                int idx = tid + i * 128;
                int rr = idx >> 3, c16 = idx & 7;
                const __half* src = srcW + (size_t)rr * K + koff + c16 * 8;
                CP_ASYNC16(tb + rr * 128 + ((c16 ^ (rr & 7)) * 16), src);
            }
        }
    };

    float acc[2][8][4];
#pragma unroll
    for (int mt = 0; mt < 2; mt++)
#pragma unroll
        for (int nt = 0; nt < 8; nt++)
#pragma unroll
            for (int j = 0; j < 4; j++)
                acc[mt][nt][j] = 0.f;

    const int arow  = wid * 32 + (lane & 15);
    const int ahalf = lane >> 4;
    const int brow  = ((lane >> 4) << 3) + (lane & 7);
    const int bhalf = (lane >> 3) & 1;

    issue_stage(0, 0); CP_COMMIT();

#pragma unroll 1
    for (int kc = 0; kc < NC; kc++) {
        if (kc + 1 < NC) issue_stage(kc + 1, (kc + 1) & 1);
        CP_COMMIT();
        CP_WAIT1();
        __syncthreads();

        const uint32_t stb = sb + (kc & 1) * STAGE_B;
        const uint32_t tAh = stb;
        const uint32_t tAl = stb + A_T_BYTES;
        const uint32_t tW  = stb + 2 * A_T_BYTES;

#pragma unroll
        for (int ks = 0; ks < 4; ks++) {
            uint32_t ahi[2][4], alo[2][4], bf[4][4];
#pragma unroll
            for (int mt = 0; mt < 2; mt++) {
                int r  = arow + mt * 16;
                int ch = 2 * ks + ahalf;
                uint32_t off = r * 128 + ((ch ^ (r & 7)) * 16);
                LDSM_X4(ahi[mt], tAh + off);
                LDSM_X4(alo[mt], tAl + off);
            }
#pragma unroll
            for (int nt2 = 0; nt2 < 4; nt2++) {
                int r  = brow + nt2 * 16;
                int ch = 2 * ks + bhalf;
                uint32_t off = r * 128 + ((ch ^ (r & 7)) * 16);
                LDSM_X4(bf[nt2], tW + off);
            }
#pragma unroll
            for (int mt = 0; mt < 2; mt++)
#pragma unroll
                for (int nt = 0; nt < 8; nt++) {
                    const uint32_t* bv = &bf[nt >> 1][(nt & 1) * 2];
                    MMA16816H(acc[mt][nt], ahi[mt], bv[0], bv[1]);
                    MMA16816H(acc[mt][nt], alo[mt], bv[0], bv[1]);
                }
        }
        __syncthreads();
    }

#pragma unroll
    for (int mt = 0; mt < 2; mt++) {
        int row0 = bm0 + wid * 32 + mt * 16 + (lane >> 2);
#pragma unroll
        for (int nt = 0; nt < 8; nt++) {
            int col = bn0 + nt * 8 + (lane & 3) * 2;
            float b0 = bias[col], b1 = bias[col + 1];
            float2 o0 = { acc[mt][nt][0] + b0, acc[mt][nt][1] + b1 };
            float2 o1 = { acc[mt][nt][2] + b0, acc[mt][nt][3] + b1 };
            *(float2*)&C[(size_t)row0 * N + col]       = o0;
            *(float2*)&C[(size_t)(row0 + 8) * N + col] = o1;
        }
    }
}

// ===========================================================================
// Persistent layer-1 recurrence (unchanged from R11)
// ===========================================================================
#define REC1_SMEM ((32 * 260 + 32 * 260) * 4)   // 66560 B

__global__ __launch_bounds__(256, 1)
void lstm_rec1(const float* __restrict__ pre,   // [16][128][1024]
               const float* __restrict__ Whh,   // [1024][256]
               float* __restrict__ y1,          // [16][128][256]
               __half* __restrict__ y1hi,
               __half* __restrict__ y1lo)
{
    extern __shared__ __align__(1024) float sm1[];
    float* ws = sm1;                  // [32][260]
    float* hs = sm1 + 32 * 260;       // [32][260]
    const uint32_t hs_b = smem_u32(hs);

    const int tid = threadIdx.x;
    const int bq  = blockIdx.x >> 5;
    const int ug  = blockIdx.x & 31;
    const int u0  = ug * 8;
    const int b0  = bq * 32;

    const int u  = tid & 7;
    const int bl = tid >> 3;

    for (int i = tid; i < 32 * 256; i += 256) {
        int lr = i >> 8, k = i & 255;
        int g = lr >> 3, uu = lr & 7;
        ws[lr * 260 + k] = Whh[(size_t)(g * HH1 + u0 + uu) * HH1 + k];
    }
    unsigned lgen = 0;
    if (tid == 0) lgen = *(volatile unsigned*)&g_bgen[bq * 32];
    __syncthreads();

    const ulonglong2* h2 = (const ulonglong2*)(hs + bl * 260);
    const ulonglong2* w2[4];
#pragma unroll
    for (int g = 0; g < 4; g++)
        w2[g] = (const ulonglong2*)(ws + (g * 8 + u) * 260);

    float c = 0.f;

#pragma unroll 1
    for (int t = 0; t < T_STEPS; t++) {
        const float* prow = pre + ((size_t)t * BATCH + b0 + bl) * (4 * HH1) + u0 + u;
        float p0 = prow[0], p1 = prow[HH1], p2 = prow[2 * HH1], p3 = prow[3 * HH1];

        float a0 = 0.f, a1 = 0.f, a2 = 0.f, a3 = 0.f;
        if (t > 0) {
            const float* hsrc = y1 + (size_t)(t - 1) * BATCH * HH1 + (size_t)b0 * HH1;
#pragma unroll
            for (int i = 0; i < 8; i++) {
                int flat = tid + i * 256;
                int row = flat >> 6;
                int c16 = flat & 63;
                CP_ASYNC16(hs_b + row * 1040 + c16 * 16,
                           hsrc + row * HH1 + c16 * 4);
            }
            CP_COMMIT(); CP_WAIT0();
            __syncthreads();

            unsigned long long acc2[4][2] = {{0,0},{0,0},{0,0},{0,0}};
#pragma unroll 8
            for (int k4 = 0; k4 < 64; k4++) {
                ulonglong2 hv = h2[k4];
#pragma unroll
                for (int g = 0; g < 4; g++) {
                    ulonglong2 wv = w2[g][k4];
                    FMA_F32X2(acc2[g][0], hv.x, wv.x);
                    FMA_F32X2(acc2[g][1], hv.y, wv.y);
                }
            }
            a0 = unpack_sum(acc2[0][0]) + unpack_sum(acc2[0][1]);
            a1 = unpack_sum(acc2[1][0]) + unpack_sum(acc2[1][1]);
            a2 = unpack_sum(acc2[2][0]) + unpack_sum(acc2[2][1]);
            a3 = unpack_sum(acc2[3][0]) + unpack_sum(acc2[3][1]);
        }

        float gi = p0 + a0, gf = p1 + a1, gg = p2 + a2, go = p3 + a3;
        float si = 1.f / (1.f + __expf(-gi));
        float sf = 1.f / (1.f + __expf(-gf));
        float so = 1.f / (1.f + __expf(-go));
        float tg = tanhf(gg);
        c = sf * c + si * tg;
        float h = so * tanhf(c);

        size_t oi = ((size_t)t * BATCH + b0 + bl) * HH1 + u0 + u;
        y1[oi] = h;
        __half hb = __float2half_rn(h);
        y1hi[oi] = hb;
        y1lo[oi] = __float2half_rn(h - __half2float(hb));

        if (t < T_STEPS - 1)
            grid_sync_q(lgen, &g_bcnt[bq * 32], &g_bgen[bq * 32], 32);
    }
}

// ===========================================================================
// Persistent layer-2 recurrence, TENSORIZED (3-pass fp16 split, near-exact).
// Grid 128 = 4 batch-quarters x 32 unit-groups (16 units each).
// Block 256 thr (8 warps as 2m x 4n). Per step:
//   G[32b x 64row] = Hq[32x512](hi,lo fp16) @ Wg[64x512](hi,lo fp16)^T
//   passes: Hhi*Whi + Hhi*Wlo + Hlo*Whi.
// W stationary/swizzled in smem; h staged via per-quarter global fp16 + cp.async.
// ===========================================================================
#define RC2_W_B (8 * 64 * 128)           // 64 KB per W component
#define RC2_H_B (8 * 32 * 128)           // 32 KB per h component
#define REC2_SMEM (2 * RC2_W_B + 2 * RC2_H_B + 64 * 33 * 4)   // 205056 B

__global__ __launch_bounds__(256, 1)
void lstm_rec2_mma(const float* __restrict__ pre,   // [16][128][2048]
                   const float* __restrict__ Whh,   // [2048][512]
                   float* __restrict__ out,         // [16][128][512]
                   __half* __restrict__ h2hi,       // [4][32][512]
                   __half* __restrict__ h2lo)
{
    extern __shared__ __align__(1024) char sm2[];
    const uint32_t sb   = smem_u32(sm2);
    const uint32_t sWhi = sb;
    const uint32_t sWlo = sb + RC2_W_B;
    const uint32_t sHhi = sb + 2 * RC2_W_B;
    const uint32_t sHlo = sb + 2 * RC2_W_B + RC2_H_B;
    float* G = (float*)(sm2 + 2 * RC2_W_B + 2 * RC2_H_B);   // [64][33]

    const int tid  = threadIdx.x;
    const int lane = tid & 31;
    const int wid  = tid >> 5;
    const int wm   = wid & 1;            // m half (16 batches)
    const int wn   = wid >> 1;           // 0..3 (16 gate-rows each)
    const int bq   = blockIdx.x >> 5;
    const int ug   = blockIdx.x & 31;
    const int u0   = ug * 16;
    const int b0   = bq * 32;

    __half* h2hi_q = h2hi + (size_t)bq * 32 * HH2;
    __half* h2lo_q = h2lo + (size_t)bq * 32 * HH2;

    // stationary W: split fp32 -> (hi,lo) fp16, swizzled k-chunked layout
    for (int i = tid; i < 4096; i += 256) {          // 16B chunks
        int r  = i >> 6;                              // gate-row 0..63
        int ch = i & 63;                              // 8-half chunk in row
        int g = r >> 4, uu = r & 15;
        const float* wsrc = Whh + (size_t)(g * HH2 + u0 + uu) * HH2 + ch * 8;
        __align__(16) __half hi8[8], lo8[8];
#pragma unroll
        for (int j = 0; j < 8; j++) {
            float f = wsrc[j];
            hi8[j] = __float2half_rn(f);
            lo8[j] = __float2half_rn(f - __half2float(hi8[j]));
        }
        int kc = ch >> 3, c8 = ch & 7;
        uint32_t off = kc * (64 * 128) + r * 128 + ((c8 ^ (r & 7)) * 16);
        *(uint4*)(sm2 + (sWhi - sb) + off) = *(uint4*)hi8;
        *(uint4*)(sm2 + (sWlo - sb) + off) = *(uint4*)lo8;
    }
    unsigned lgen = 0;
    if (tid == 0) lgen = *(volatile unsigned*)&g_bgen[bq * 32];
    __syncthreads();

    // gate-phase cell ownership: u = tid&15, batches bb and bb+16
    const int u  = tid & 15;
    const int bb = tid >> 4;
    float c0 = 0.f, c1 = 0.f;

    // mma lane addressing
    const int arow  = wm * 16 + (lane & 15);
    const int ahalf = lane >> 4;
    const int brow  = wn * 16 + ((lane >> 4) << 3) + (lane & 7);
    const int bhalf = (lane >> 3) & 1;

#pragma unroll 1
    for (int t = 0; t < T_STEPS; t++) {
        // hoist pre-gate loads
        const float* prowA = pre + ((size_t)t * BATCH + b0 + bb) * (4 * HH2) + u0 + u;
        const float* prowB = prowA + (size_t)16 * 4 * HH2;
        float pA[4], pB[4];
#pragma unroll
        for (int g = 0; g < 4; g++) { pA[g] = prowA[g * HH2]; pB[g] = prowB[g * HH2]; }

        if (t > 0) {
            // stage h (hi,lo) fp16: 2048+2048 chunks of 16B
#pragma unroll
            for (int i = 0; i < 8; i++) {
                int flat = tid + i * 256;            // 0..2047
                int row = flat >> 6;                 // batch 0..31
                int ch  = flat & 63;
                int kc = ch >> 3, c8 = ch & 7;
                uint32_t off = kc * (32 * 128) + row * 128 + ((c8 ^ (row & 7)) * 16);
                CP_ASYNC16(sHhi + off, h2hi_q + row * HH2 + ch * 8);
                CP_ASYNC16(sHlo + off, h2lo_q + row * HH2 + ch * 8);
            }
            CP_COMMIT(); CP_WAIT0();
            __syncthreads();

            float acc[2][4];
#pragma unroll
            for (int nt = 0; nt < 2; nt++)
#pragma unroll
                for (int j = 0; j < 4; j++) acc[nt][j] = 0.f;

#pragma unroll 4
            for (int ks = 0; ks < 32; ks++) {
                const int kc = ks >> 2;
                uint32_t ah[4], al[4], bh[4], blo[4];
                {
                    int ch = 2 * (ks & 3) + ahalf;
                    uint32_t off = kc * (32 * 128) + arow * 128 + ((ch ^ (arow & 7)) * 16);
                    LDSM_X4(ah, sHhi + off);
                    LDSM_X4(al, sHlo + off);
                }
                {
                    int ch = 2 * (ks & 3) + bhalf;
                    uint32_t off = kc * (64 * 128) + brow * 128 + ((ch ^ (brow & 7)) * 16);
                    LDSM_X4(bh, sWhi + off);
                    LDSM_X4(blo, sWlo + off);
                }
#pragma unroll
                for (int nt = 0; nt < 2; nt++) {
                    MMA16816H(acc[nt], ah, bh[nt * 2], bh[nt * 2 + 1]);
                    MMA16816H(acc[nt], ah, blo[nt * 2], blo[nt * 2 + 1]);
                    MMA16816H(acc[nt], al, bh[nt * 2], bh[nt * 2 + 1]);
                }
            }

            // exchange: G[gate_row][batch]
#pragma unroll
            for (int nt = 0; nt < 2; nt++) {
                int col = wn * 16 + nt * 8 + (lane & 3) * 2;
                int row = wm * 16 + (lane >> 2);
                G[col * 33 + row]           = acc[nt][0];
                G[(col + 1) * 33 + row]     = acc[nt][1];
                G[col * 33 + row + 8]       = acc[nt][2];
                G[(col + 1) * 33 + row + 8] = acc[nt][3];
            }
            __syncthreads();
        }

        float aA[4] = {0, 0, 0, 0}, aB[4] = {0, 0, 0, 0};
        if (t > 0) {
#pragma unroll
            for (int g = 0; g < 4; g++) {
                aA[g] = G[(g * 16 + u) * 33 + bb];
                aB[g] = G[(g * 16 + u) * 33 + bb + 16];
            }
        }

        {
            float gi = pA[0] + aA[0], gf = pA[1] + aA[1];
            float gg = pA[2] + aA[2], go = pA[3] + aA[3];
            float si = 1.f / (1.f + __expf(-gi));
            float sf = 1.f / (1.f + __expf(-gf));
            float so = 1.f / (1.f + __expf(-go));
            float tg = tanhf(gg);
            c0 = sf * c0 + si * tg;
            float h = so * tanhf(c0);
            out[((size_t)t * BATCH + b0 + bb) * HH2 + u0 + u] = h;
            __half hb = __float2half_rn(h);
            h2hi_q[bb * HH2 + u0 + u] = hb;
            h2lo_q[bb * HH2 + u0 + u] = __float2half_rn(h - __half2float(hb));
        }
        {
            float gi = pB[0] + aB[0], gf = pB[1] + aB[1];
            float gg = pB[2] + aB[2], go = pB[3] + aB[3];
            float si = 1.f / (1.f + __expf(-gi));
            float sf = 1.f / (1.f + __expf(-gf));
            float so = 1.f / (1.f + __expf(-go));
            float tg = tanhf(gg);
            c1 = sf * c1 + si * tg;
            float h = so * tanhf(c1);
            out[((size_t)t * BATCH + b0 + bb + 16) * HH2 + u0 + u] = h;
            __half hb = __float2half_rn(h);
            h2hi_q[(bb + 16) * HH2 + u0 + u] = hb;
            h2lo_q[(bb + 16) * HH2 + u0 + u] = __float2half_rn(h - __half2float(hb));
        }

        if (t < T_STEPS - 1)
            grid_sync_q(lgen, &g_bcnt[bq * 32], &g_bgen[bq * 32], 32);
    }
}

// ---------------------------------------------------------------------------
extern "C" void kernel_launch(void* const* d_in, const int* in_sizes, int n_in,
                              void* d_out, int out_size)
{
    const float* inp  = (const float*)d_in[0];
    const float* Wih1 = (const float*)d_in[1];
    const float* Whh1 = (const float*)d_in[2];
    const float* b1   = (const float*)d_in[3];
    const float* Wih2 = (const float*)d_in[4];
    const float* Whh2 = (const float*)d_in[5];
    const float* b2   = (const float*)d_in[6];
    float* out = (float*)d_out;

    float *pre1, *y1, *pre2;
    cudaGetSymbolAddress((void**)&pre1, g_pre1);
    cudaGetSymbolAddress((void**)&y1,   g_y1);
    cudaGetSymbolAddress((void**)&pre2, g_pre2);

    __half *ahi, *alo, *wf, *y1hi, *y1lo, *w2f, *h2hi, *h2lo;
    cudaGetSymbolAddress((void**)&ahi,  g_Ahi);
    cudaGetSymbolAddress((void**)&alo,  g_Alo);
    cudaGetSymbolAddress((void**)&wf,   g_Wf);
    cudaGetSymbolAddress((void**)&y1hi, g_Y1hi);
    cudaGetSymbolAddress((void**)&y1lo, g_Y1lo);
    cudaGetSymbolAddress((void**)&w2f,  g_W2f);
    cudaGetSymbolAddress((void**)&h2hi, g_H2hi);
    cudaGetSymbolAddress((void**)&h2lo, g_H2lo);

    cudaFuncSetAttribute(gemm_mma_f16,
                         cudaFuncAttributeMaxDynamicSharedMemorySize, GEMM_SMEM);
    cudaFuncSetAttribute(lstm_rec1,
                         cudaFuncAttributeMaxDynamicSharedMemorySize, REC1_SMEM);
    cudaFuncSetAttribute(lstm_rec2_mma,
                         cudaFuncAttributeMaxDynamicSharedMemorySize, REC2_SMEM);

    const int M = T_STEPS * BATCH;  // 2048

    // splits: inp -> fp16 (hi,lo); Wih1, Wih2 -> fp16
    {
        int n4a = M * IN_DIM / 4;
        split_f16<<<(n4a + 255) / 256, 256>>>(inp, ahi, alo, n4a);
        int n4w = 4 * HH1 * IN_DIM / 4;
        conv_f16<<<(n4w + 255) / 256, 256>>>(Wih1, wf, n4w);
        int n4w2 = 4 * HH2 * HH1 / 4;
        conv_f16<<<(n4w2 + 255) / 256, 256>>>(Wih2, w2f, n4w2);
    }

    // Layer 1 input projection (tensor cores, fp16 2-pass): pre1 = X @ Wih1^T + b1
    gemm_mma_f16<<<dim3(4 * HH1 / 64, M / 128), 128, GEMM_SMEM>>>(
        ahi, alo, wf, b1, pre1, 4 * HH1, IN_DIM);

    // Layer 1 recurrence (persistent, emits y1 fp16 hi/lo)
    lstm_rec1<<<128, 256, REC1_SMEM>>>(pre1, Whh1, y1, y1hi, y1lo);

    // Layer 2 input projection (tensor cores, K=256): pre2 = Y1 @ Wih2^T + b2
    gemm_mma_f16<<<dim3(4 * HH2 / 64, M / 128), 128, GEMM_SMEM>>>(
        y1hi, y1lo, w2f, b2, pre2, 4 * HH2, HH1);

    // Layer 2 recurrence (persistent, tensorized; h written straight into d_out)
    lstm_rec2_mma<<<128, 256, REC2_SMEM>>>(pre2, Whh2, out, h2hi, h2lo);
}